// round 12
// baseline (speedup 1.0000x reference)
#include <cuda_runtime.h>
#include <cuda_bf16.h>
#include <math.h>
#include <stdint.h>

// ---------------- problem constants ----------------
#define B_   64
#define T_   512
#define D_   128
#define P_   3
#define H_   512
#define K_H  3
#define TOK_ 384
#define N_   510
#define MROWS (B_*N_)          // 32640
#define H3   (3*H_)            // 1536

// ---------------- device scratch ----------------
__device__ float g_aligned[B_*T_*D_];
__device__ float g_h[(size_t)MROWS*H_];
__device__ float g_gx[(size_t)MROWS*H3];
__device__ float g_hstate[2][B_][H_];     // b-major GRU state, double buffered
__device__ unsigned g_barflags[128];      // dense: 4 cache lines, one word/block

// bf16 hi/lo split buffers
__device__ __nv_bfloat16 g_tokHi[(size_t)MROWS*TOK_];
__device__ __nv_bfloat16 g_tokLo[(size_t)MROWS*TOK_];
__device__ __nv_bfloat16 g_hHi[(size_t)MROWS*H_];
__device__ __nv_bfloat16 g_hLo[(size_t)MROWS*H_];
__device__ __nv_bfloat16 g_hidHi[(size_t)MROWS*H_];
__device__ __nv_bfloat16 g_hidLo[(size_t)MROWS*H_];
__device__ __nv_bfloat16 g_actHi[(size_t)MROWS*H3];
__device__ __nv_bfloat16 g_actLo[(size_t)MROWS*H3];
__device__ __nv_bfloat16 g_pwHi[H_*TOK_],  g_pwLo[H_*TOK_];
__device__ __nv_bfloat16 g_wihHi[H3*H_],   g_wihLo[H3*H_];
__device__ __nv_bfloat16 g_w1Hi[H3*H_],    g_w1Lo[H3*H_];
__device__ __nv_bfloat16 g_w2Hi[K_H*TOK_*H_], g_w2Lo[K_H*TOK_*H_];

// =====================================================================
// helpers
// =====================================================================
__device__ __forceinline__ uint32_t smem_u32(const void* p)
{
    uint32_t a;
    asm("{ .reg .u64 t; cvta.to.shared.u64 t, %1; cvt.u32.u64 %0, t; }"
        : "=r"(a) : "l"(p));
    return a;
}

__device__ __forceinline__ void ldsm4(uint32_t* r, uint32_t addr)
{
    asm volatile("ldmatrix.sync.aligned.m8n8.x4.shared.b16 {%0,%1,%2,%3}, [%4];"
                 : "=r"(r[0]), "=r"(r[1]), "=r"(r[2]), "=r"(r[3]) : "r"(addr));
}

__device__ __forceinline__ void mma_bf16(float* c, const uint32_t* a, const uint32_t* b)
{
    asm volatile(
        "mma.sync.aligned.m16n8k16.row.col.f32.bf16.bf16.f32 "
        "{%0,%1,%2,%3}, {%4,%5,%6,%7}, {%8,%9}, {%0,%1,%2,%3};"
        : "+f"(c[0]), "+f"(c[1]), "+f"(c[2]), "+f"(c[3])
        : "r"(a[0]), "r"(a[1]), "r"(a[2]), "r"(a[3]), "r"(b[0]), "r"(b[1]));
}

// packed f32x2 ops
typedef unsigned long long ull;
__device__ __forceinline__ ull pack2(float x, float y)
{
    ull r; asm("mov.b64 %0, {%1, %2};" : "=l"(r) : "f"(x), "f"(y)); return r;
}
#define FMA2(d, a, b) asm("fma.rn.f32x2 %0, %1, %2, %0;" : "+l"(d) : "l"(a), "l"(b))

// =====================================================================
// bf16 split-precision warp-MMA GEMM (unchanged — proven, 59% tensor)
// =====================================================================
#define TEN  16384
#define STGB (4*TEN)

__global__ __launch_bounds__(256) void bgemm_kernel(
    const __nv_bfloat16* __restrict__ Ahi, const __nv_bfloat16* __restrict__ Alo, int lda,
    const __nv_bfloat16* __restrict__ Bhi, const __nv_bfloat16* __restrict__ Blo, int ldb,
    const float* __restrict__ bias,
    float* __restrict__ Cf,
    __nv_bfloat16* __restrict__ Chi, __nv_bfloat16* __restrict__ Clo,
    int ldc, int K, int epi)
{
    extern __shared__ char dsm[];
    const uint32_t sBase = smem_u32(dsm);

    const int tid  = threadIdx.x;
    const int warp = tid >> 5;
    const int lane = tid & 31;
    const int mBase = blockIdx.y << 7;
    const int nBase = blockIdx.x << 7;
    const int wm = (warp & 1) << 6;
    const int wn = (warp >> 1) << 5;

    const int ten   = tid >> 6;
    const __nv_bfloat16* tp = (ten == 0) ? Ahi : (ten == 1) ? Alo : (ten == 2) ? Bhi : Blo;
    const int ldt   = (ten < 2) ? lda : ldb;
    const int rbase = (ten < 2) ? mBase : nBase;
    const int lsub  = tid & 63;

#define STAGE(kt) do {                                                         \
    uint32_t sdst = sBase + (((kt) & 1) ? STGB : 0) + ten * TEN;               \
    const __nv_bfloat16* gsrc = tp + (size_t)rbase * ldt + ((kt) << 6);        \
    _Pragma("unroll")                                                          \
    for (int q_ = 0; q_ < 16; q_++) {                                          \
        int id_  = lsub + (q_ << 6);                                           \
        int row_ = id_ >> 3;                                                   \
        int cc_  = id_ & 7;                                                    \
        uint32_t d_ = sdst + row_ * 128 + ((cc_ ^ (row_ & 7)) << 4);           \
        const __nv_bfloat16* s_ = gsrc + (size_t)row_ * ldt + (cc_ << 3);      \
        asm volatile("cp.async.cg.shared.global [%0], [%1], 16;"               \
                     :: "r"(d_), "l"(s_));                                     \
    }                                                                          \
} while (0)

    float acc[4][4][4];
#pragma unroll
    for (int mt = 0; mt < 4; mt++)
#pragma unroll
        for (int nt = 0; nt < 4; nt++)
#pragma unroll
            for (int c = 0; c < 4; c++) acc[mt][nt][c] = 0.f;

    const int nk = K >> 6;
    STAGE(0);
    asm volatile("cp.async.commit_group;");

    const int lane16 = lane & 15;
    const int lanehi = lane >> 4;
    const int brow_off = (lane & 7) + ((lane >> 4) << 3);
    const int bchi     = (lane >> 3) & 1;

    for (int kt = 0; kt < nk; kt++) {
        if (kt + 1 < nk) STAGE(kt + 1);
        asm volatile("cp.async.commit_group;");
        asm volatile("cp.async.wait_group 1;");
        __syncthreads();

        const uint32_t buf = sBase + ((kt & 1) ? STGB : 0);
        const uint32_t sAh = buf, sAl = buf + TEN, sBh = buf + 2*TEN, sBl = buf + 3*TEN;

#pragma unroll
        for (int ks = 0; ks < 4; ks++) {
            uint32_t ah[4][4], al[4][4], bh[4][2], bl[4][2];
#pragma unroll
            for (int mt = 0; mt < 4; mt++) {
                int row = wm + mt*16 + lane16;
                uint32_t off = (uint32_t)(row * 128 + (((ks*2 + lanehi) ^ (row & 7)) << 4));
                ldsm4(ah[mt], sAh + off);
                ldsm4(al[mt], sAl + off);
            }
#pragma unroll
            for (int np = 0; np < 2; np++) {
                int row = wn + np*16 + brow_off;
                uint32_t off = (uint32_t)(row * 128 + (((ks*2 + bchi) ^ (row & 7)) << 4));
                uint32_t r4[4];
                ldsm4(r4, sBh + off);
                bh[np*2][0] = r4[0]; bh[np*2][1] = r4[1];
                bh[np*2+1][0] = r4[2]; bh[np*2+1][1] = r4[3];
                ldsm4(r4, sBl + off);
                bl[np*2][0] = r4[0]; bl[np*2][1] = r4[1];
                bl[np*2+1][0] = r4[2]; bl[np*2+1][1] = r4[3];
            }
#pragma unroll
            for (int mt = 0; mt < 4; mt++)
#pragma unroll
                for (int nt = 0; nt < 4; nt++) {
                    mma_bf16(acc[mt][nt], ah[mt], bh[nt]);
                    mma_bf16(acc[mt][nt], ah[mt], bl[nt]);
                    mma_bf16(acc[mt][nt], al[mt], bh[nt]);
                }
        }
        __syncthreads();
    }
#undef STAGE

    const int g = lane >> 2;
    const int t = lane & 3;
#pragma unroll
    for (int mt = 0; mt < 4; mt++) {
        int r0 = mBase + wm + mt*16 + g;
#pragma unroll
        for (int nt = 0; nt < 4; nt++) {
            int c0 = nBase + wn + nt*8 + 2*t;
            float b0 = __ldg(bias + c0);
            float b1 = __ldg(bias + c0 + 1);
            float v00 = acc[mt][nt][0] + b0;
            float v01 = acc[mt][nt][1] + b1;
            float v10 = acc[mt][nt][2] + b0;
            float v11 = acc[mt][nt][3] + b1;
            if (epi == 0) {
                *(float2*)(Cf + (size_t)r0 * ldc + c0)       = make_float2(v00, v01);
                *(float2*)(Cf + (size_t)(r0 + 8) * ldc + c0) = make_float2(v10, v11);
            } else {
                v00 = 0.5f * v00 * (1.0f + erff(v00 * 0.70710678118654752f));
                v01 = 0.5f * v01 * (1.0f + erff(v01 * 0.70710678118654752f));
                v10 = 0.5f * v10 * (1.0f + erff(v10 * 0.70710678118654752f));
                v11 = 0.5f * v11 * (1.0f + erff(v11 * 0.70710678118654752f));
                __nv_bfloat16 h00 = __float2bfloat16(v00);
                __nv_bfloat16 h01 = __float2bfloat16(v01);
                __nv_bfloat16 h10 = __float2bfloat16(v10);
                __nv_bfloat16 h11 = __float2bfloat16(v11);
                __nv_bfloat162 hi0; hi0.x = h00; hi0.y = h01;
                __nv_bfloat162 hi1; hi1.x = h10; hi1.y = h11;
                __nv_bfloat162 lo0; lo0.x = __float2bfloat16(v00 - __bfloat162float(h00));
                                    lo0.y = __float2bfloat16(v01 - __bfloat162float(h01));
                __nv_bfloat162 lo1; lo1.x = __float2bfloat16(v10 - __bfloat162float(h10));
                                    lo1.y = __float2bfloat16(v11 - __bfloat162float(h11));
                *(__nv_bfloat162*)(Chi + (size_t)r0 * ldc + c0)       = hi0;
                *(__nv_bfloat162*)(Chi + (size_t)(r0 + 8) * ldc + c0) = hi1;
                *(__nv_bfloat162*)(Clo + (size_t)r0 * ldc + c0)       = lo0;
                *(__nv_bfloat162*)(Clo + (size_t)(r0 + 8) * ldc + c0) = lo1;
            }
        }
    }
}

// =====================================================================
// fp32->bf16 hi/lo split (weights)
// =====================================================================
__global__ void split_kernel(const float4* __restrict__ src,
                             uint2* __restrict__ hi, uint2* __restrict__ lo, int n4)
{
    int i = blockIdx.x * blockDim.x + threadIdx.x;
    if (i >= n4) return;
    float4 v = src[i];
    __nv_bfloat16 h[4], l[4];
    h[0] = __float2bfloat16(v.x); l[0] = __float2bfloat16(v.x - __bfloat162float(h[0]));
    h[1] = __float2bfloat16(v.y); l[1] = __float2bfloat16(v.y - __bfloat162float(h[1]));
    h[2] = __float2bfloat16(v.z); l[2] = __float2bfloat16(v.z - __bfloat162float(h[2]));
    h[3] = __float2bfloat16(v.w); l[3] = __float2bfloat16(v.w - __bfloat162float(h[3]));
    hi[i] = *(uint2*)h;
    lo[i] = *(uint2*)l;
}

// =====================================================================
// fp32 tiled SGEMM (session alignment only)
// =====================================================================
#define BM 128
#define BN 64
#define BK 16

__global__ __launch_bounds__(256) void sgemm_kernel(
    const float* __restrict__ A, int lda,
    const float* __restrict__ Bm, int ldb,
    const float* __restrict__ bias,
    float* __restrict__ C, int ldc,
    int M, int N, int K,
    const int* __restrict__ sidx,
    size_t strideAb, size_t strideCb, size_t strideBsel, size_t strideBiasSel)
{
    __shared__ __align__(16) float As[BK][BM + 4];
    __shared__ __align__(16) float Bs[BK][BN + 4];

    if (sidx) {
        int bz = blockIdx.z;
        A    += (size_t)bz * strideAb;
        C    += (size_t)bz * strideCb;
        int s = __ldg(&sidx[bz]);
        Bm   += (size_t)s * strideBsel;
        bias += (size_t)s * strideBiasSel;
    }

    const int tid   = threadIdx.x;
    const int mBase = blockIdx.y * BM;
    const int nBase = blockIdx.x * BN;
    const int tm    = (tid / 16) * 8;
    const int tn    = (tid % 16) * 4;

    float acc[8][4];
#pragma unroll
    for (int i = 0; i < 8; i++)
#pragma unroll
        for (int j = 0; j < 4; j++) acc[i][j] = 0.f;

    for (int k0 = 0; k0 < K; k0 += BK) {
#pragma unroll
        for (int it = 0; it < 2; it++) {
            int l  = tid + it * 256;
            int m  = l >> 2;
            int kq = (l & 3) * 4;
            float4 v = *(const float4*)(A + (size_t)(mBase + m) * lda + k0 + kq);
            As[kq + 0][m] = v.x; As[kq + 1][m] = v.y;
            As[kq + 2][m] = v.z; As[kq + 3][m] = v.w;
        }
        {
            int l  = tid;
            int n  = l >> 2;
            int kq = (l & 3) * 4;
            float4 v = *(const float4*)(Bm + (size_t)(nBase + n) * ldb + k0 + kq);
            Bs[kq + 0][n] = v.x; Bs[kq + 1][n] = v.y;
            Bs[kq + 2][n] = v.z; Bs[kq + 3][n] = v.w;
        }
        __syncthreads();

#pragma unroll
        for (int kk = 0; kk < BK; kk++) {
            float4 a0 = *(const float4*)&As[kk][tm];
            float4 a1 = *(const float4*)&As[kk][tm + 4];
            float4 b0 = *(const float4*)&Bs[kk][tn];
            float av[8] = {a0.x, a0.y, a0.z, a0.w, a1.x, a1.y, a1.z, a1.w};
            float bv[4] = {b0.x, b0.y, b0.z, b0.w};
#pragma unroll
            for (int i = 0; i < 8; i++)
#pragma unroll
                for (int j = 0; j < 4; j++) acc[i][j] += av[i] * bv[j];
        }
        __syncthreads();
    }

    float bb[4];
#pragma unroll
    for (int j = 0; j < 4; j++) bb[j] = bias[nBase + tn + j];

#pragma unroll
    for (int i = 0; i < 8; i++) {
        *(float4*)(C + (size_t)(mBase + tm + i) * ldc + nBase + tn) =
            make_float4(acc[i][0] + bb[0], acc[i][1] + bb[1],
                        acc[i][2] + bb[2], acc[i][3] + bb[3]);
    }
}

// =====================================================================
// tokens gather + bf16 hi/lo split fused
// =====================================================================
__global__ void tokens_split_kernel(float* __restrict__ out_tokens,
                                    __nv_bfloat16* __restrict__ tokHi,
                                    __nv_bfloat16* __restrict__ tokLo)
{
    int idx = blockIdx.x * blockDim.x + threadIdx.x;
    if (idx >= MROWS * TOK_) return;
    int t   = idx % TOK_;
    int row = idx / TOK_;
    int n   = row % N_;
    int b   = row / N_;
    int d   = t / P_;
    int p   = t % P_;
    float v = g_aligned[((size_t)(b * T_ + n + p)) * D_ + d];
    out_tokens[idx] = v;
    __nv_bfloat16 h = __float2bfloat16(v);
    tokHi[idx] = h;
    tokLo[idx] = __float2bfloat16(v - __bfloat162float(h));
}

// =====================================================================
// RMS norm + bf16 hi/lo split fused
// =====================================================================
__global__ __launch_bounds__(128) void rms_split_kernel(
    const float* __restrict__ scale,
    __nv_bfloat16* __restrict__ hHi, __nv_bfloat16* __restrict__ hLo)
{
    int row = blockIdx.x;
    const float* h = g_h + (size_t)row * H_;
    int tid = threadIdx.x;

    float4 x = *(const float4*)(h + tid * 4);
    float ss = x.x * x.x + x.y * x.y + x.z * x.z + x.w * x.w;
#pragma unroll
    for (int o = 16; o; o >>= 1) ss += __shfl_xor_sync(0xffffffffu, ss, o);

    __shared__ float wsum[4];
    if ((tid & 31) == 0) wsum[tid >> 5] = ss;
    __syncthreads();
    float tot = wsum[0] + wsum[1] + wsum[2] + wsum[3];
    float inv = rsqrtf(tot * (1.0f / H_) + 1e-6f);

    float4 sc = *(const float4*)(scale + tid * 4);
    float v[4] = { x.x * inv * sc.x, x.y * inv * sc.y,
                   x.z * inv * sc.z, x.w * inv * sc.w };
    __nv_bfloat16 hi[4], lo[4];
#pragma unroll
    for (int j = 0; j < 4; j++) {
        hi[j] = __float2bfloat16(v[j]);
        lo[j] = __float2bfloat16(v[j] - __bfloat162float(hi[j]));
    }
    *(uint2*)(hHi + (size_t)row * H_ + tid * 4) = *(uint2*)hi;
    *(uint2*)(hLo + (size_t)row * H_ + tid * 4) = *(uint2*)lo;
}

// =====================================================================
// GRU v3: same compute layout as v2 (proven), NEW contention-free barrier:
// each block writes its own dense flag word (st.release.gpu), then 128
// threads poll the 128 flags in parallel (ld.acquire.gpu). No atomics.
// The entry __threadfence() (gpu scope -> CCTL.IVALL) both orders the
// state STGs and invalidates L1D so the next step's cp.async.ca staging
// reads are coherent with remote-SM writes.
// =====================================================================
#define GRU_BLOCKS 128
#define HSH_LD 516

__global__ void gru_init_kernel()
{
    int idx = blockIdx.x * blockDim.x + threadIdx.x;
    float* p = &g_hstate[0][0][0];
    if (idx < 2 * B_ * H_) p[idx] = 0.f;
    if (idx < GRU_BLOCKS) g_barflags[idx] = 0u;
}

__device__ __forceinline__ void gbar(unsigned gen)
{
    __threadfence();          // order state writes; invalidate L1D
    __syncthreads();
    if (threadIdx.x == 0) {
        asm volatile("st.release.gpu.u32 [%0], %1;"
                     :: "l"(&g_barflags[blockIdx.x]), "r"(gen) : "memory");
    }
    if (threadIdx.x < GRU_BLOCKS) {
        unsigned v;
        do {
            asm volatile("ld.acquire.gpu.u32 %0, [%1];"
                         : "=r"(v) : "l"(&g_barflags[threadIdx.x]) : "memory");
        } while (v < gen);
    }
    __syncthreads();
}

__global__ __launch_bounds__(256, 1) void gru_kernel(
    const float* __restrict__ Whh, const float* __restrict__ bhh,
    __nv_bfloat16* __restrict__ hidHi, __nv_bfloat16* __restrict__ hidLo)
{
    extern __shared__ char gsm[];
    ull*   ws2  = (ull*)gsm;                       // [512*24]   98304 B
    ull*   red  = ws2 + 512*24;                    // [16*16*24] 49152 B
    float* hsh  = (float*)(red + 16*16*24);        // [16*HSH_LD] 33024 B
    float* sbhh = hsh + 16*HSH_LD;                 // [48]

    const int bid  = blockIdx.x;
    const int cg   = bid >> 2;
    const int bg   = bid & 3;
    const int tid  = threadIdx.x;
    const int col0 = cg * 16;

    for (int i = tid; i < 512*24; i += 256) {
        int k = i / 24, j = i % 24;
        int g  = j >> 3;
        int cp = (j & 7) << 1;
        float w0 = Whh[(size_t)(g*H_ + col0 + cp)     * H_ + k];
        float w1 = Whh[(size_t)(g*H_ + col0 + cp + 1) * H_ + k];
        ws2[i] = pack2(w0, w1);
    }
    if (tid < 48) {
        int g = tid >> 4, c = tid & 15;
        sbhh[tid] = bhh[g*H_ + col0 + c];
    }
    __syncthreads();

    const int lb  = tid & 15;
    const int kq  = tid >> 4;
    const int oc  = tid & 15;
    const int ob  = tid >> 4;
    const int gbo = bg * 16 + ob;
    const int ocol = col0 + oc;

    int cur = 0;
    for (int n = 0; n < N_; n++) {
        // stage h slice (16 b x 512) coalesced into smem
#pragma unroll
        for (int q = 0; q < 8; q++) {
            int fi  = tid * 8 + q;
            int bb  = fi >> 7;
            int kk4 = fi & 127;
            uint32_t dst = smem_u32(&hsh[bb * HSH_LD + kk4 * 4]);
            const float* src = &g_hstate[cur][bg*16 + bb][kk4 * 4];
            asm volatile("cp.async.ca.shared.global [%0], [%1], 16;"
                         :: "r"(dst), "l"(src));
        }
        asm volatile("cp.async.commit_group;");

        // gx prefetch overlaps the staging latency
        const float* gx = g_gx + ((size_t)(gbo * N_ + n)) * H3;
        float gxr = __ldg(gx + ocol);
        float gxz = __ldg(gx + H_ + ocol);
        float gxn = __ldg(gx + 2*H_ + ocol);

        asm volatile("cp.async.wait_group 0;");
        __syncthreads();

        ull acc2[24];
#pragma unroll
        for (int j = 0; j < 24; j++) acc2[j] = 0ull;

        const float* hr = &hsh[lb * HSH_LD + kq * 32];
        const ull*   wb = &ws2[(kq * 32) * 24];
#pragma unroll 8
        for (int kk = 0; kk < 32; kk++) {
            float hv = hr[kk];
            ull h2 = pack2(hv, hv);
            const ulonglong2* w = (const ulonglong2*)(wb + kk * 24);
#pragma unroll
            for (int jj = 0; jj < 12; jj++) {
                ulonglong2 wv = w[jj];
                FMA2(acc2[2*jj],     h2, wv.x);
                FMA2(acc2[2*jj + 1], h2, wv.y);
            }
        }

        {
            ulonglong2* rp = (ulonglong2*)&red[(size_t)(kq * 16 + lb) * 24];
#pragma unroll
            for (int jj = 0; jj < 12; jj++)
                rp[jj] = make_ulonglong2(acc2[2*jj], acc2[2*jj + 1]);
        }
        float hp = hsh[ob * HSH_LD + ocol];
        __syncthreads();

        const float* rf = (const float*)red;
        float s0 = 0.f, s1 = 0.f, s2 = 0.f;
#pragma unroll
        for (int q = 0; q < 16; q++) {
            const float* r = rf + (size_t)(q * 16 + ob) * 48;
            s0 += r[oc];
            s1 += r[16 + oc];
            s2 += r[32 + oc];
        }
        float r  = 1.0f / (1.0f + expf(-(gxr + s0 + sbhh[oc])));
        float z  = 1.0f / (1.0f + expf(-(gxz + s1 + sbhh[16 + oc])));
        float nn = tanhf(gxn + r * (s2 + sbhh[32 + oc]));
        float hn = (1.0f - z) * nn + z * hp;

        g_hstate[cur ^ 1][gbo][ocol] = hn;
        __nv_bfloat16 oh = __float2bfloat16(hn);
        size_t base = ((size_t)(gbo * N_ + n)) * H_ + ocol;
        hidHi[base] = oh;
        hidLo[base] = __float2bfloat16(hn - __bfloat162float(oh));

        gbar((unsigned)(n + 1));
        cur ^= 1;
    }
}

// =====================================================================
// host side
// =====================================================================
#define BG_DSMEM  (2 * STGB)                                   // 131072 B
#define GRU_DSMEM (512*24*8 + 16*16*24*8 + 16*HSH_LD*4 + 48*4) // 180672 B

static void launch_split(const float* src, __nv_bfloat16* hi, __nv_bfloat16* lo, size_t n)
{
    int n4 = (int)(n / 4);
    split_kernel<<<(n4 + 255) / 256, 256>>>((const float4*)src, (uint2*)hi, (uint2*)lo, n4);
}

extern "C" void kernel_launch(void* const* d_in, const int* in_sizes, int n_in,
                              void* d_out, int out_size)
{
    const float* x      = (const float*)d_in[0];
    const int*   sidx   = (const int*)  d_in[1];
    const float* sW     = (const float*)d_in[2];
    const float* sb     = (const float*)d_in[3];
    const float* projW  = (const float*)d_in[4];
    const float* projb  = (const float*)d_in[5];
    const float* rscale = (const float*)d_in[6];
    const float* Wih    = (const float*)d_in[7];
    const float* Whh    = (const float*)d_in[8];
    const float* bih    = (const float*)d_in[9];
    const float* bhh    = (const float*)d_in[10];
    const float* W1     = (const float*)d_in[11];
    const float* b1     = (const float*)d_in[12];
    const float* W2     = (const float*)d_in[13];
    const float* b2     = (const float*)d_in[14];

    float* out        = (float*)d_out;
    float* out_preds  = out;
    float* out_tokens = out + (size_t)K_H * MROWS * TOK_;

    float *pAligned, *pH, *pGx;
    cudaGetSymbolAddress((void**)&pAligned, g_aligned);
    cudaGetSymbolAddress((void**)&pH,       g_h);
    cudaGetSymbolAddress((void**)&pGx,      g_gx);

    __nv_bfloat16 *tokHi, *tokLo, *hHi, *hLo, *hidHi, *hidLo, *actHi, *actLo;
    __nv_bfloat16 *pwHi, *pwLo, *wihHi, *wihLo, *w1Hi, *w1Lo, *w2Hi, *w2Lo;
    cudaGetSymbolAddress((void**)&tokHi, g_tokHi); cudaGetSymbolAddress((void**)&tokLo, g_tokLo);
    cudaGetSymbolAddress((void**)&hHi,   g_hHi);   cudaGetSymbolAddress((void**)&hLo,   g_hLo);
    cudaGetSymbolAddress((void**)&hidHi, g_hidHi); cudaGetSymbolAddress((void**)&hidLo, g_hidLo);
    cudaGetSymbolAddress((void**)&actHi, g_actHi); cudaGetSymbolAddress((void**)&actLo, g_actLo);
    cudaGetSymbolAddress((void**)&pwHi,  g_pwHi);  cudaGetSymbolAddress((void**)&pwLo,  g_pwLo);
    cudaGetSymbolAddress((void**)&wihHi, g_wihHi); cudaGetSymbolAddress((void**)&wihLo, g_wihLo);
    cudaGetSymbolAddress((void**)&w1Hi,  g_w1Hi);  cudaGetSymbolAddress((void**)&w1Lo,  g_w1Lo);
    cudaGetSymbolAddress((void**)&w2Hi,  g_w2Hi);  cudaGetSymbolAddress((void**)&w2Lo,  g_w2Lo);

    static int attr_set = 0;
    if (!attr_set) {
        cudaFuncSetAttribute(bgemm_kernel,
                             cudaFuncAttributeMaxDynamicSharedMemorySize, BG_DSMEM);
        cudaFuncSetAttribute(gru_kernel,
                             cudaFuncAttributeMaxDynamicSharedMemorySize, GRU_DSMEM);
        attr_set = 1;
    }

    // 0) proj weight split
    launch_split(projW, pwHi, pwLo, (size_t)H_ * TOK_);

    // 1) session alignment (fp32 — feeds tokens output)
    sgemm_kernel<<<dim3(D_ / BN, T_ / BM, B_), 256>>>(
        x, D_, sW, D_, sb, pAligned, D_,
        T_, D_, D_,
        sidx, (size_t)T_ * D_, (size_t)T_ * D_, (size_t)D_ * D_, (size_t)D_);

    // 2) tokens gather + split (fused)
    tokens_split_kernel<<<(MROWS * TOK_ + 255) / 256, 256>>>(out_tokens, tokHi, tokLo);

    // 3) proj GEMM
    bgemm_kernel<<<dim3(H_ / 128, MROWS / 128), 256, BG_DSMEM>>>(
        tokHi, tokLo, TOK_, pwHi, pwLo, TOK_, projb,
        pH, nullptr, nullptr, H_, TOK_, 0);

    // 4) RMS + split (fused)
    rms_split_kernel<<<MROWS, 128>>>(rscale, hHi, hLo);

    // 5) Wih split
    launch_split(Wih, wihHi, wihLo, (size_t)H3 * H_);

    // 6) gx = h @ Wih^T + bih
    bgemm_kernel<<<dim3(H3 / 128, MROWS / 128), 256, BG_DSMEM>>>(
        hHi, hLo, H_, wihHi, wihLo, H_, bih,
        pGx, nullptr, nullptr, H3, H_, 0);

    launch_split(W1, w1Hi, w1Lo, (size_t)H3 * H_);
    launch_split(W2, w2Hi, w2Lo, (size_t)K_H * TOK_ * H_);

    // 7) GRU recurrence (bf16 hi/lo hidden out)
    gru_init_kernel<<<(2 * B_ * H_ + 255) / 256, 256>>>();
    gru_kernel<<<GRU_BLOCKS, 256, GRU_DSMEM>>>(Whh, bhh, hidHi, hidLo);

    // 8) head1 (3 horizons fused, N=1536) + exact GELU -> bf16 hi/lo
    bgemm_kernel<<<dim3(H3 / 128, MROWS / 128), 256, BG_DSMEM>>>(
        hidHi, hidLo, H_, w1Hi, w1Lo, H_, b1,
        nullptr, actHi, actLo, H3, H_, 1);

    // 9) head2 per horizon -> preds
    for (int k = 0; k < K_H; k++) {
        bgemm_kernel<<<dim3(TOK_ / 128, MROWS / 128), 256, BG_DSMEM>>>(
            actHi + (size_t)k * H_, actLo + (size_t)k * H_, H3,
            w2Hi + (size_t)k * TOK_ * H_, w2Lo + (size_t)k * TOK_ * H_, H_,
            b2 + (size_t)k * TOK_,
            out_preds + (size_t)k * MROWS * TOK_, nullptr, nullptr, TOK_, H_, 0);
    }
}

// round 14
// speedup vs baseline: 1.5422x; 1.5422x over previous
#include <cuda_runtime.h>
#include <cuda_bf16.h>
#include <math.h>
#include <stdint.h>

// ---------------- problem constants ----------------
#define B_   64
#define T_   512
#define D_   128
#define P_   3
#define H_   512
#define K_H  3
#define TOK_ 384
#define N_   510
#define MROWS (B_*N_)          // 32640
#define H3   (3*H_)            // 1536

// ---------------- device scratch ----------------
__device__ float g_aligned[B_*T_*D_];
__device__ float g_h[(size_t)MROWS*H_];
__device__ float g_gx[(size_t)MROWS*H3];
__device__ float g_hstate[2][B_][H_];     // b-major GRU state, double buffered
__device__ unsigned g_gctr[4*32];         // one counter per batch-group, 128B apart

// bf16 hi/lo split buffers
__device__ __nv_bfloat16 g_tokHi[(size_t)MROWS*TOK_];
__device__ __nv_bfloat16 g_tokLo[(size_t)MROWS*TOK_];
__device__ __nv_bfloat16 g_hHi[(size_t)MROWS*H_];
__device__ __nv_bfloat16 g_hLo[(size_t)MROWS*H_];
__device__ __nv_bfloat16 g_hidHi[(size_t)MROWS*H_];
__device__ __nv_bfloat16 g_hidLo[(size_t)MROWS*H_];
__device__ __nv_bfloat16 g_actHi[(size_t)MROWS*H3];
__device__ __nv_bfloat16 g_actLo[(size_t)MROWS*H3];
__device__ __nv_bfloat16 g_pwHi[H_*TOK_],  g_pwLo[H_*TOK_];
__device__ __nv_bfloat16 g_wihHi[H3*H_],   g_wihLo[H3*H_];
__device__ __nv_bfloat16 g_w1Hi[H3*H_],    g_w1Lo[H3*H_];
__device__ __nv_bfloat16 g_w2Hi[K_H*TOK_*H_], g_w2Lo[K_H*TOK_*H_];

// =====================================================================
// helpers
// =====================================================================
__device__ __forceinline__ uint32_t smem_u32(const void* p)
{
    uint32_t a;
    asm("{ .reg .u64 t; cvta.to.shared.u64 t, %1; cvt.u32.u64 %0, t; }"
        : "=r"(a) : "l"(p));
    return a;
}

__device__ __forceinline__ void ldsm4(uint32_t* r, uint32_t addr)
{
    asm volatile("ldmatrix.sync.aligned.m8n8.x4.shared.b16 {%0,%1,%2,%3}, [%4];"
                 : "=r"(r[0]), "=r"(r[1]), "=r"(r[2]), "=r"(r[3]) : "r"(addr));
}

__device__ __forceinline__ void mma_bf16(float* c, const uint32_t* a, const uint32_t* b)
{
    asm volatile(
        "mma.sync.aligned.m16n8k16.row.col.f32.bf16.bf16.f32 "
        "{%0,%1,%2,%3}, {%4,%5,%6,%7}, {%8,%9}, {%0,%1,%2,%3};"
        : "+f"(c[0]), "+f"(c[1]), "+f"(c[2]), "+f"(c[3])
        : "r"(a[0]), "r"(a[1]), "r"(a[2]), "r"(a[3]), "r"(b[0]), "r"(b[1]));
}

// packed f32x2 ops
typedef unsigned long long ull;
__device__ __forceinline__ ull pack2(float x, float y)
{
    ull r; asm("mov.b64 %0, {%1, %2};" : "=l"(r) : "f"(x), "f"(y)); return r;
}
#define FMA2(d, a, b) asm("fma.rn.f32x2 %0, %1, %2, %0;" : "+l"(d) : "l"(a), "l"(b))

// =====================================================================
// bf16 split-precision warp-MMA GEMM (unchanged — proven, 59% tensor)
// =====================================================================
#define TEN  16384
#define STGB (4*TEN)

__global__ __launch_bounds__(256) void bgemm_kernel(
    const __nv_bfloat16* __restrict__ Ahi, const __nv_bfloat16* __restrict__ Alo, int lda,
    const __nv_bfloat16* __restrict__ Bhi, const __nv_bfloat16* __restrict__ Blo, int ldb,
    const float* __restrict__ bias,
    float* __restrict__ Cf,
    __nv_bfloat16* __restrict__ Chi, __nv_bfloat16* __restrict__ Clo,
    int ldc, int K, int epi)
{
    extern __shared__ char dsm[];
    const uint32_t sBase = smem_u32(dsm);

    const int tid  = threadIdx.x;
    const int warp = tid >> 5;
    const int lane = tid & 31;
    const int mBase = blockIdx.y << 7;
    const int nBase = blockIdx.x << 7;
    const int wm = (warp & 1) << 6;
    const int wn = (warp >> 1) << 5;

    const int ten   = tid >> 6;
    const __nv_bfloat16* tp = (ten == 0) ? Ahi : (ten == 1) ? Alo : (ten == 2) ? Bhi : Blo;
    const int ldt   = (ten < 2) ? lda : ldb;
    const int rbase = (ten < 2) ? mBase : nBase;
    const int lsub  = tid & 63;

#define STAGE(kt) do {                                                         \
    uint32_t sdst = sBase + (((kt) & 1) ? STGB : 0) + ten * TEN;               \
    const __nv_bfloat16* gsrc = tp + (size_t)rbase * ldt + ((kt) << 6);        \
    _Pragma("unroll")                                                          \
    for (int q_ = 0; q_ < 16; q_++) {                                          \
        int id_  = lsub + (q_ << 6);                                           \
        int row_ = id_ >> 3;                                                   \
        int cc_  = id_ & 7;                                                    \
        uint32_t d_ = sdst + row_ * 128 + ((cc_ ^ (row_ & 7)) << 4);           \
        const __nv_bfloat16* s_ = gsrc + (size_t)row_ * ldt + (cc_ << 3);      \
        asm volatile("cp.async.cg.shared.global [%0], [%1], 16;"               \
                     :: "r"(d_), "l"(s_));                                     \
    }                                                                          \
} while (0)

    float acc[4][4][4];
#pragma unroll
    for (int mt = 0; mt < 4; mt++)
#pragma unroll
        for (int nt = 0; nt < 4; nt++)
#pragma unroll
            for (int c = 0; c < 4; c++) acc[mt][nt][c] = 0.f;

    const int nk = K >> 6;
    STAGE(0);
    asm volatile("cp.async.commit_group;");

    const int lane16 = lane & 15;
    const int lanehi = lane >> 4;
    const int brow_off = (lane & 7) + ((lane >> 4) << 3);
    const int bchi     = (lane >> 3) & 1;

    for (int kt = 0; kt < nk; kt++) {
        if (kt + 1 < nk) STAGE(kt + 1);
        asm volatile("cp.async.commit_group;");
        asm volatile("cp.async.wait_group 1;");
        __syncthreads();

        const uint32_t buf = sBase + ((kt & 1) ? STGB : 0);
        const uint32_t sAh = buf, sAl = buf + TEN, sBh = buf + 2*TEN, sBl = buf + 3*TEN;

#pragma unroll
        for (int ks = 0; ks < 4; ks++) {
            uint32_t ah[4][4], al[4][4], bh[4][2], bl[4][2];
#pragma unroll
            for (int mt = 0; mt < 4; mt++) {
                int row = wm + mt*16 + lane16;
                uint32_t off = (uint32_t)(row * 128 + (((ks*2 + lanehi) ^ (row & 7)) << 4));
                ldsm4(ah[mt], sAh + off);
                ldsm4(al[mt], sAl + off);
            }
#pragma unroll
            for (int np = 0; np < 2; np++) {
                int row = wn + np*16 + brow_off;
                uint32_t off = (uint32_t)(row * 128 + (((ks*2 + bchi) ^ (row & 7)) << 4));
                uint32_t r4[4];
                ldsm4(r4, sBh + off);
                bh[np*2][0] = r4[0]; bh[np*2][1] = r4[1];
                bh[np*2+1][0] = r4[2]; bh[np*2+1][1] = r4[3];
                ldsm4(r4, sBl + off);
                bl[np*2][0] = r4[0]; bl[np*2][1] = r4[1];
                bl[np*2+1][0] = r4[2]; bl[np*2+1][1] = r4[3];
            }
#pragma unroll
            for (int mt = 0; mt < 4; mt++)
#pragma unroll
                for (int nt = 0; nt < 4; nt++) {
                    mma_bf16(acc[mt][nt], ah[mt], bh[nt]);
                    mma_bf16(acc[mt][nt], ah[mt], bl[nt]);
                    mma_bf16(acc[mt][nt], al[mt], bh[nt]);
                }
        }
        __syncthreads();
    }
#undef STAGE

    const int g = lane >> 2;
    const int t = lane & 3;
#pragma unroll
    for (int mt = 0; mt < 4; mt++) {
        int r0 = mBase + wm + mt*16 + g;
#pragma unroll
        for (int nt = 0; nt < 4; nt++) {
            int c0 = nBase + wn + nt*8 + 2*t;
            float b0 = __ldg(bias + c0);
            float b1 = __ldg(bias + c0 + 1);
            float v00 = acc[mt][nt][0] + b0;
            float v01 = acc[mt][nt][1] + b1;
            float v10 = acc[mt][nt][2] + b0;
            float v11 = acc[mt][nt][3] + b1;
            if (epi == 0) {
                *(float2*)(Cf + (size_t)r0 * ldc + c0)       = make_float2(v00, v01);
                *(float2*)(Cf + (size_t)(r0 + 8) * ldc + c0) = make_float2(v10, v11);
            } else {
                v00 = 0.5f * v00 * (1.0f + erff(v00 * 0.70710678118654752f));
                v01 = 0.5f * v01 * (1.0f + erff(v01 * 0.70710678118654752f));
                v10 = 0.5f * v10 * (1.0f + erff(v10 * 0.70710678118654752f));
                v11 = 0.5f * v11 * (1.0f + erff(v11 * 0.70710678118654752f));
                __nv_bfloat16 h00 = __float2bfloat16(v00);
                __nv_bfloat16 h01 = __float2bfloat16(v01);
                __nv_bfloat16 h10 = __float2bfloat16(v10);
                __nv_bfloat16 h11 = __float2bfloat16(v11);
                __nv_bfloat162 hi0; hi0.x = h00; hi0.y = h01;
                __nv_bfloat162 hi1; hi1.x = h10; hi1.y = h11;
                __nv_bfloat162 lo0; lo0.x = __float2bfloat16(v00 - __bfloat162float(h00));
                                    lo0.y = __float2bfloat16(v01 - __bfloat162float(h01));
                __nv_bfloat162 lo1; lo1.x = __float2bfloat16(v10 - __bfloat162float(h10));
                                    lo1.y = __float2bfloat16(v11 - __bfloat162float(h11));
                *(__nv_bfloat162*)(Chi + (size_t)r0 * ldc + c0)       = hi0;
                *(__nv_bfloat162*)(Chi + (size_t)(r0 + 8) * ldc + c0) = hi1;
                *(__nv_bfloat162*)(Clo + (size_t)r0 * ldc + c0)       = lo0;
                *(__nv_bfloat162*)(Clo + (size_t)(r0 + 8) * ldc + c0) = lo1;
            }
        }
    }
}

// =====================================================================
// fp32->bf16 hi/lo split (weights)
// =====================================================================
__global__ void split_kernel(const float4* __restrict__ src,
                             uint2* __restrict__ hi, uint2* __restrict__ lo, int n4)
{
    int i = blockIdx.x * blockDim.x + threadIdx.x;
    if (i >= n4) return;
    float4 v = src[i];
    __nv_bfloat16 h[4], l[4];
    h[0] = __float2bfloat16(v.x); l[0] = __float2bfloat16(v.x - __bfloat162float(h[0]));
    h[1] = __float2bfloat16(v.y); l[1] = __float2bfloat16(v.y - __bfloat162float(h[1]));
    h[2] = __float2bfloat16(v.z); l[2] = __float2bfloat16(v.z - __bfloat162float(h[2]));
    h[3] = __float2bfloat16(v.w); l[3] = __float2bfloat16(v.w - __bfloat162float(h[3]));
    hi[i] = *(uint2*)h;
    lo[i] = *(uint2*)l;
}

// =====================================================================
// fp32 tiled SGEMM (session alignment only)
// =====================================================================
#define BM 128
#define BN 64
#define BK 16

__global__ __launch_bounds__(256) void sgemm_kernel(
    const float* __restrict__ A, int lda,
    const float* __restrict__ Bm, int ldb,
    const float* __restrict__ bias,
    float* __restrict__ C, int ldc,
    int M, int N, int K,
    const int* __restrict__ sidx,
    size_t strideAb, size_t strideCb, size_t strideBsel, size_t strideBiasSel)
{
    __shared__ __align__(16) float As[BK][BM + 4];
    __shared__ __align__(16) float Bs[BK][BN + 4];

    if (sidx) {
        int bz = blockIdx.z;
        A    += (size_t)bz * strideAb;
        C    += (size_t)bz * strideCb;
        int s = __ldg(&sidx[bz]);
        Bm   += (size_t)s * strideBsel;
        bias += (size_t)s * strideBiasSel;
    }

    const int tid   = threadIdx.x;
    const int mBase = blockIdx.y * BM;
    const int nBase = blockIdx.x * BN;
    const int tm    = (tid / 16) * 8;
    const int tn    = (tid % 16) * 4;

    float acc[8][4];
#pragma unroll
    for (int i = 0; i < 8; i++)
#pragma unroll
        for (int j = 0; j < 4; j++) acc[i][j] = 0.f;

    for (int k0 = 0; k0 < K; k0 += BK) {
#pragma unroll
        for (int it = 0; it < 2; it++) {
            int l  = tid + it * 256;
            int m  = l >> 2;
            int kq = (l & 3) * 4;
            float4 v = *(const float4*)(A + (size_t)(mBase + m) * lda + k0 + kq);
            As[kq + 0][m] = v.x; As[kq + 1][m] = v.y;
            As[kq + 2][m] = v.z; As[kq + 3][m] = v.w;
        }
        {
            int l  = tid;
            int n  = l >> 2;
            int kq = (l & 3) * 4;
            float4 v = *(const float4*)(Bm + (size_t)(nBase + n) * ldb + k0 + kq);
            Bs[kq + 0][n] = v.x; Bs[kq + 1][n] = v.y;
            Bs[kq + 2][n] = v.z; Bs[kq + 3][n] = v.w;
        }
        __syncthreads();

#pragma unroll
        for (int kk = 0; kk < BK; kk++) {
            float4 a0 = *(const float4*)&As[kk][tm];
            float4 a1 = *(const float4*)&As[kk][tm + 4];
            float4 b0 = *(const float4*)&Bs[kk][tn];
            float av[8] = {a0.x, a0.y, a0.z, a0.w, a1.x, a1.y, a1.z, a1.w};
            float bv[4] = {b0.x, b0.y, b0.z, b0.w};
#pragma unroll
            for (int i = 0; i < 8; i++)
#pragma unroll
                for (int j = 0; j < 4; j++) acc[i][j] += av[i] * bv[j];
        }
        __syncthreads();
    }

    float bb[4];
#pragma unroll
    for (int j = 0; j < 4; j++) bb[j] = bias[nBase + tn + j];

#pragma unroll
    for (int i = 0; i < 8; i++) {
        *(float4*)(C + (size_t)(mBase + tm + i) * ldc + nBase + tn) =
            make_float4(acc[i][0] + bb[0], acc[i][1] + bb[1],
                        acc[i][2] + bb[2], acc[i][3] + bb[3]);
    }
}

// =====================================================================
// tokens gather + bf16 hi/lo split fused
// =====================================================================
__global__ void tokens_split_kernel(float* __restrict__ out_tokens,
                                    __nv_bfloat16* __restrict__ tokHi,
                                    __nv_bfloat16* __restrict__ tokLo)
{
    int idx = blockIdx.x * blockDim.x + threadIdx.x;
    if (idx >= MROWS * TOK_) return;
    int t   = idx % TOK_;
    int row = idx / TOK_;
    int n   = row % N_;
    int b   = row / N_;
    int d   = t / P_;
    int p   = t % P_;
    float v = g_aligned[((size_t)(b * T_ + n + p)) * D_ + d];
    out_tokens[idx] = v;
    __nv_bfloat16 h = __float2bfloat16(v);
    tokHi[idx] = h;
    tokLo[idx] = __float2bfloat16(v - __bfloat162float(h));
}

// =====================================================================
// RMS norm + bf16 hi/lo split fused
// =====================================================================
__global__ __launch_bounds__(128) void rms_split_kernel(
    const float* __restrict__ scale,
    __nv_bfloat16* __restrict__ hHi, __nv_bfloat16* __restrict__ hLo)
{
    int row = blockIdx.x;
    const float* h = g_h + (size_t)row * H_;
    int tid = threadIdx.x;

    float4 x = *(const float4*)(h + tid * 4);
    float ss = x.x * x.x + x.y * x.y + x.z * x.z + x.w * x.w;
#pragma unroll
    for (int o = 16; o; o >>= 1) ss += __shfl_xor_sync(0xffffffffu, ss, o);

    __shared__ float wsum[4];
    if ((tid & 31) == 0) wsum[tid >> 5] = ss;
    __syncthreads();
    float tot = wsum[0] + wsum[1] + wsum[2] + wsum[3];
    float inv = rsqrtf(tot * (1.0f / H_) + 1e-6f);

    float4 sc = *(const float4*)(scale + tid * 4);
    float v[4] = { x.x * inv * sc.x, x.y * inv * sc.y,
                   x.z * inv * sc.z, x.w * inv * sc.w };
    __nv_bfloat16 hi[4], lo[4];
#pragma unroll
    for (int j = 0; j < 4; j++) {
        hi[j] = __float2bfloat16(v[j]);
        lo[j] = __float2bfloat16(v[j] - __bfloat162float(hi[j]));
    }
    *(uint2*)(hHi + (size_t)row * H_ + tid * 4) = *(uint2*)hi;
    *(uint2*)(hLo + (size_t)row * H_ + tid * 4) = *(uint2*)lo;
}

// =====================================================================
// GRU v4: compute layout = v2 (proven). Barrier = R7 atomic counter,
// but SCOPED to the 32-block batch-group (blocks sharing bg form a
// closed dependency group): 4 independent counters on separate cache
// lines; arrival chain 32 instead of 128. Staging uses cp.async.cg
// (L2-only) so coherence never depends on L1 invalidation.
// =====================================================================
#define GRU_BLOCKS 128
#define HSH_LD 516

__global__ void gru_init_kernel()
{
    int idx = blockIdx.x * blockDim.x + threadIdx.x;
    float* p = &g_hstate[0][0][0];
    if (idx < 2 * B_ * H_) p[idx] = 0.f;
    if (idx < 4*32) g_gctr[idx] = 0u;
}

__device__ __forceinline__ void gbar_group(unsigned* ctr, unsigned target)
{
    __threadfence();          // order state STGs (gpu scope)
    __syncthreads();
    if (threadIdx.x == 0) {
        atomicAdd(ctr, 1u);
        unsigned v;
        do {
            asm volatile("ld.acquire.gpu.u32 %0, [%1];" : "=r"(v) : "l"(ctr));
        } while (v < target);
    }
    __syncthreads();
}

__global__ __launch_bounds__(256, 1) void gru_kernel(
    const float* __restrict__ Whh, const float* __restrict__ bhh,
    __nv_bfloat16* __restrict__ hidHi, __nv_bfloat16* __restrict__ hidLo)
{
    extern __shared__ char gsm[];
    ull*   ws2  = (ull*)gsm;                       // [512*24]   98304 B
    ull*   red  = ws2 + 512*24;                    // [16*16*24] 49152 B
    float* hsh  = (float*)(red + 16*16*24);        // [16*HSH_LD] 33024 B
    float* sbhh = hsh + 16*HSH_LD;                 // [48]

    const int bid  = blockIdx.x;
    const int cg   = bid >> 2;
    const int bg   = bid & 3;
    const int tid  = threadIdx.x;
    const int col0 = cg * 16;
    unsigned* myctr = &g_gctr[bg * 32];

    for (int i = tid; i < 512*24; i += 256) {
        int k = i / 24, j = i % 24;
        int g  = j >> 3;
        int cp = (j & 7) << 1;
        float w0 = Whh[(size_t)(g*H_ + col0 + cp)     * H_ + k];
        float w1 = Whh[(size_t)(g*H_ + col0 + cp + 1) * H_ + k];
        ws2[i] = pack2(w0, w1);
    }
    if (tid < 48) {
        int g = tid >> 4, c = tid & 15;
        sbhh[tid] = bhh[g*H_ + col0 + c];
    }
    __syncthreads();

    const int lb  = tid & 15;
    const int kq  = tid >> 4;
    const int oc  = tid & 15;
    const int ob  = tid >> 4;
    const int gbo = bg * 16 + ob;
    const int ocol = col0 + oc;

    int cur = 0;
    for (int n = 0; n < N_; n++) {
        // stage h slice (16 b x 512) coalesced into smem (L2-only)
#pragma unroll
        for (int q = 0; q < 8; q++) {
            int fi  = tid * 8 + q;
            int bb  = fi >> 7;
            int kk4 = fi & 127;
            uint32_t dst = smem_u32(&hsh[bb * HSH_LD + kk4 * 4]);
            const float* src = &g_hstate[cur][bg*16 + bb][kk4 * 4];
            asm volatile("cp.async.cg.shared.global [%0], [%1], 16;"
                         :: "r"(dst), "l"(src));
        }
        asm volatile("cp.async.commit_group;");

        // gx prefetch overlaps the staging latency
        const float* gx = g_gx + ((size_t)(gbo * N_ + n)) * H3;
        float gxr = __ldg(gx + ocol);
        float gxz = __ldg(gx + H_ + ocol);
        float gxn = __ldg(gx + 2*H_ + ocol);

        asm volatile("cp.async.wait_group 0;");
        __syncthreads();

        ull acc2[24];
#pragma unroll
        for (int j = 0; j < 24; j++) acc2[j] = 0ull;

        const float* hr = &hsh[lb * HSH_LD + kq * 32];
        const ull*   wb = &ws2[(kq * 32) * 24];
#pragma unroll 8
        for (int kk = 0; kk < 32; kk++) {
            float hv = hr[kk];
            ull h2 = pack2(hv, hv);
            const ulonglong2* w = (const ulonglong2*)(wb + kk * 24);
#pragma unroll
            for (int jj = 0; jj < 12; jj++) {
                ulonglong2 wv = w[jj];
                FMA2(acc2[2*jj],     h2, wv.x);
                FMA2(acc2[2*jj + 1], h2, wv.y);
            }
        }

        {
            ulonglong2* rp = (ulonglong2*)&red[(size_t)(kq * 16 + lb) * 24];
#pragma unroll
            for (int jj = 0; jj < 12; jj++)
                rp[jj] = make_ulonglong2(acc2[2*jj], acc2[2*jj + 1]);
        }
        float hp = hsh[ob * HSH_LD + ocol];
        __syncthreads();

        const float* rf = (const float*)red;
        float s0 = 0.f, s1 = 0.f, s2 = 0.f;
#pragma unroll
        for (int q = 0; q < 16; q++) {
            const float* r = rf + (size_t)(q * 16 + ob) * 48;
            s0 += r[oc];
            s1 += r[16 + oc];
            s2 += r[32 + oc];
        }
        float r  = 1.0f / (1.0f + expf(-(gxr + s0 + sbhh[oc])));
        float z  = 1.0f / (1.0f + expf(-(gxz + s1 + sbhh[16 + oc])));
        float nn = tanhf(gxn + r * (s2 + sbhh[32 + oc]));
        float hn = (1.0f - z) * nn + z * hp;

        g_hstate[cur ^ 1][gbo][ocol] = hn;
        __nv_bfloat16 oh = __float2bfloat16(hn);
        size_t base = ((size_t)(gbo * N_ + n)) * H_ + ocol;
        hidHi[base] = oh;
        hidLo[base] = __float2bfloat16(hn - __bfloat162float(oh));

        gbar_group(myctr, (unsigned)(n + 1) * 32u);
        cur ^= 1;
    }
}

// =====================================================================
// host side
// =====================================================================
#define BG_DSMEM  (2 * STGB)                                   // 131072 B
#define GRU_DSMEM (512*24*8 + 16*16*24*8 + 16*HSH_LD*4 + 48*4) // 180672 B

static void launch_split(const float* src, __nv_bfloat16* hi, __nv_bfloat16* lo, size_t n)
{
    int n4 = (int)(n / 4);
    split_kernel<<<(n4 + 255) / 256, 256>>>((const float4*)src, (uint2*)hi, (uint2*)lo, n4);
}

extern "C" void kernel_launch(void* const* d_in, const int* in_sizes, int n_in,
                              void* d_out, int out_size)
{
    const float* x      = (const float*)d_in[0];
    const int*   sidx   = (const int*)  d_in[1];
    const float* sW     = (const float*)d_in[2];
    const float* sb     = (const float*)d_in[3];
    const float* projW  = (const float*)d_in[4];
    const float* projb  = (const float*)d_in[5];
    const float* rscale = (const float*)d_in[6];
    const float* Wih    = (const float*)d_in[7];
    const float* Whh    = (const float*)d_in[8];
    const float* bih    = (const float*)d_in[9];
    const float* bhh    = (const float*)d_in[10];
    const float* W1     = (const float*)d_in[11];
    const float* b1     = (const float*)d_in[12];
    const float* W2     = (const float*)d_in[13];
    const float* b2     = (const float*)d_in[14];

    float* out        = (float*)d_out;
    float* out_preds  = out;
    float* out_tokens = out + (size_t)K_H * MROWS * TOK_;

    float *pAligned, *pH, *pGx;
    cudaGetSymbolAddress((void**)&pAligned, g_aligned);
    cudaGetSymbolAddress((void**)&pH,       g_h);
    cudaGetSymbolAddress((void**)&pGx,      g_gx);

    __nv_bfloat16 *tokHi, *tokLo, *hHi, *hLo, *hidHi, *hidLo, *actHi, *actLo;
    __nv_bfloat16 *pwHi, *pwLo, *wihHi, *wihLo, *w1Hi, *w1Lo, *w2Hi, *w2Lo;
    cudaGetSymbolAddress((void**)&tokHi, g_tokHi); cudaGetSymbolAddress((void**)&tokLo, g_tokLo);
    cudaGetSymbolAddress((void**)&hHi,   g_hHi);   cudaGetSymbolAddress((void**)&hLo,   g_hLo);
    cudaGetSymbolAddress((void**)&hidHi, g_hidHi); cudaGetSymbolAddress((void**)&hidLo, g_hidLo);
    cudaGetSymbolAddress((void**)&actHi, g_actHi); cudaGetSymbolAddress((void**)&actLo, g_actLo);
    cudaGetSymbolAddress((void**)&pwHi,  g_pwHi);  cudaGetSymbolAddress((void**)&pwLo,  g_pwLo);
    cudaGetSymbolAddress((void**)&wihHi, g_wihHi); cudaGetSymbolAddress((void**)&wihLo, g_wihLo);
    cudaGetSymbolAddress((void**)&w1Hi,  g_w1Hi);  cudaGetSymbolAddress((void**)&w1Lo,  g_w1Lo);
    cudaGetSymbolAddress((void**)&w2Hi,  g_w2Hi);  cudaGetSymbolAddress((void**)&w2Lo,  g_w2Lo);

    static int attr_set = 0;
    if (!attr_set) {
        cudaFuncSetAttribute(bgemm_kernel,
                             cudaFuncAttributeMaxDynamicSharedMemorySize, BG_DSMEM);
        cudaFuncSetAttribute(gru_kernel,
                             cudaFuncAttributeMaxDynamicSharedMemorySize, GRU_DSMEM);
        attr_set = 1;
    }

    // 0) proj weight split
    launch_split(projW, pwHi, pwLo, (size_t)H_ * TOK_);

    // 1) session alignment (fp32 — feeds tokens output)
    sgemm_kernel<<<dim3(D_ / BN, T_ / BM, B_), 256>>>(
        x, D_, sW, D_, sb, pAligned, D_,
        T_, D_, D_,
        sidx, (size_t)T_ * D_, (size_t)T_ * D_, (size_t)D_ * D_, (size_t)D_);

    // 2) tokens gather + split (fused)
    tokens_split_kernel<<<(MROWS * TOK_ + 255) / 256, 256>>>(out_tokens, tokHi, tokLo);

    // 3) proj GEMM
    bgemm_kernel<<<dim3(H_ / 128, MROWS / 128), 256, BG_DSMEM>>>(
        tokHi, tokLo, TOK_, pwHi, pwLo, TOK_, projb,
        pH, nullptr, nullptr, H_, TOK_, 0);

    // 4) RMS + split (fused)
    rms_split_kernel<<<MROWS, 128>>>(rscale, hHi, hLo);

    // 5) Wih split
    launch_split(Wih, wihHi, wihLo, (size_t)H3 * H_);

    // 6) gx = h @ Wih^T + bih
    bgemm_kernel<<<dim3(H3 / 128, MROWS / 128), 256, BG_DSMEM>>>(
        hHi, hLo, H_, wihHi, wihLo, H_, bih,
        pGx, nullptr, nullptr, H3, H_, 0);

    launch_split(W1, w1Hi, w1Lo, (size_t)H3 * H_);
    launch_split(W2, w2Hi, w2Lo, (size_t)K_H * TOK_ * H_);

    // 7) GRU recurrence (bf16 hi/lo hidden out)
    gru_init_kernel<<<(2 * B_ * H_ + 255) / 256, 256>>>();
    gru_kernel<<<GRU_BLOCKS, 256, GRU_DSMEM>>>(Whh, bhh, hidHi, hidLo);

    // 8) head1 (3 horizons fused, N=1536) + exact GELU -> bf16 hi/lo
    bgemm_kernel<<<dim3(H3 / 128, MROWS / 128), 256, BG_DSMEM>>>(
        hidHi, hidLo, H_, w1Hi, w1Lo, H_, b1,
        nullptr, actHi, actLo, H3, H_, 1);

    // 9) head2 per horizon -> preds
    for (int k = 0; k < K_H; k++) {
        bgemm_kernel<<<dim3(TOK_ / 128, MROWS / 128), 256, BG_DSMEM>>>(
            actHi + (size_t)k * H_, actLo + (size_t)k * H_, H3,
            w2Hi + (size_t)k * TOK_ * H_, w2Lo + (size_t)k * TOK_ * H_, H_,
            b2 + (size_t)k * TOK_,
            out_preds + (size_t)k * MROWS * TOK_, nullptr, nullptr, TOK_, H_, 0);
    }
}

// round 15
// speedup vs baseline: 2.1280x; 1.3799x over previous
#include <cuda_runtime.h>
#include <cuda_bf16.h>
#include <math.h>
#include <stdint.h>

// ---------------- problem constants ----------------
#define B_   64
#define T_   512
#define D_   128
#define P_   3
#define H_   512
#define K_H  3
#define TOK_ 384
#define N_   510
#define MROWS (B_*N_)          // 32640
#define H3   (3*H_)            // 1536

// ---------------- device scratch ----------------
__device__ float g_aligned[B_*T_*D_];
__device__ float g_h[(size_t)MROWS*H_];
__device__ float g_gx[(size_t)MROWS*H3];
__device__ __nv_bfloat16 g_hsHi[2][B_][H_];   // GRU state bf16 hi, double buffered
__device__ __nv_bfloat16 g_hsLo[2][B_][H_];   // GRU state bf16 lo
__device__ unsigned g_gctr[4*32];             // one counter per batch-group, 128B apart

// bf16 hi/lo split buffers
__device__ __nv_bfloat16 g_tokHi[(size_t)MROWS*TOK_];
__device__ __nv_bfloat16 g_tokLo[(size_t)MROWS*TOK_];
__device__ __nv_bfloat16 g_hHi[(size_t)MROWS*H_];
__device__ __nv_bfloat16 g_hLo[(size_t)MROWS*H_];
__device__ __nv_bfloat16 g_hidHi[(size_t)MROWS*H_];
__device__ __nv_bfloat16 g_hidLo[(size_t)MROWS*H_];
__device__ __nv_bfloat16 g_actHi[(size_t)MROWS*H3];
__device__ __nv_bfloat16 g_actLo[(size_t)MROWS*H3];
__device__ __nv_bfloat16 g_pwHi[H_*TOK_],  g_pwLo[H_*TOK_];
__device__ __nv_bfloat16 g_wihHi[H3*H_],   g_wihLo[H3*H_];
__device__ __nv_bfloat16 g_whhHi[H3*H_],   g_whhLo[H3*H_];
__device__ __nv_bfloat16 g_w1Hi[H3*H_],    g_w1Lo[H3*H_];
__device__ __nv_bfloat16 g_w2Hi[K_H*TOK_*H_], g_w2Lo[K_H*TOK_*H_];

// =====================================================================
// helpers
// =====================================================================
__device__ __forceinline__ uint32_t smem_u32(const void* p)
{
    uint32_t a;
    asm("{ .reg .u64 t; cvta.to.shared.u64 t, %1; cvt.u32.u64 %0, t; }"
        : "=r"(a) : "l"(p));
    return a;
}

__device__ __forceinline__ void ldsm4(uint32_t* r, uint32_t addr)
{
    asm volatile("ldmatrix.sync.aligned.m8n8.x4.shared.b16 {%0,%1,%2,%3}, [%4];"
                 : "=r"(r[0]), "=r"(r[1]), "=r"(r[2]), "=r"(r[3]) : "r"(addr));
}

__device__ __forceinline__ void mma_bf16(float* c, const uint32_t* a, const uint32_t* b)
{
    asm volatile(
        "mma.sync.aligned.m16n8k16.row.col.f32.bf16.bf16.f32 "
        "{%0,%1,%2,%3}, {%4,%5,%6,%7}, {%8,%9}, {%0,%1,%2,%3};"
        : "+f"(c[0]), "+f"(c[1]), "+f"(c[2]), "+f"(c[3])
        : "r"(a[0]), "r"(a[1]), "r"(a[2]), "r"(a[3]), "r"(b[0]), "r"(b[1]));
}

// =====================================================================
// bf16 split-precision warp-MMA GEMM (unchanged — proven, 59% tensor)
// =====================================================================
#define TEN  16384
#define STGB (4*TEN)

__global__ __launch_bounds__(256) void bgemm_kernel(
    const __nv_bfloat16* __restrict__ Ahi, const __nv_bfloat16* __restrict__ Alo, int lda,
    const __nv_bfloat16* __restrict__ Bhi, const __nv_bfloat16* __restrict__ Blo, int ldb,
    const float* __restrict__ bias,
    float* __restrict__ Cf,
    __nv_bfloat16* __restrict__ Chi, __nv_bfloat16* __restrict__ Clo,
    int ldc, int K, int epi)
{
    extern __shared__ char dsm[];
    const uint32_t sBase = smem_u32(dsm);

    const int tid  = threadIdx.x;
    const int warp = tid >> 5;
    const int lane = tid & 31;
    const int mBase = blockIdx.y << 7;
    const int nBase = blockIdx.x << 7;
    const int wm = (warp & 1) << 6;
    const int wn = (warp >> 1) << 5;

    const int ten   = tid >> 6;
    const __nv_bfloat16* tp = (ten == 0) ? Ahi : (ten == 1) ? Alo : (ten == 2) ? Bhi : Blo;
    const int ldt   = (ten < 2) ? lda : ldb;
    const int rbase = (ten < 2) ? mBase : nBase;
    const int lsub  = tid & 63;

#define STAGE(kt) do {                                                         \
    uint32_t sdst = sBase + (((kt) & 1) ? STGB : 0) + ten * TEN;               \
    const __nv_bfloat16* gsrc = tp + (size_t)rbase * ldt + ((kt) << 6);        \
    _Pragma("unroll")                                                          \
    for (int q_ = 0; q_ < 16; q_++) {                                          \
        int id_  = lsub + (q_ << 6);                                           \
        int row_ = id_ >> 3;                                                   \
        int cc_  = id_ & 7;                                                    \
        uint32_t d_ = sdst + row_ * 128 + ((cc_ ^ (row_ & 7)) << 4);           \
        const __nv_bfloat16* s_ = gsrc + (size_t)row_ * ldt + (cc_ << 3);      \
        asm volatile("cp.async.cg.shared.global [%0], [%1], 16;"               \
                     :: "r"(d_), "l"(s_));                                     \
    }                                                                          \
} while (0)

    float acc[4][4][4];
#pragma unroll
    for (int mt = 0; mt < 4; mt++)
#pragma unroll
        for (int nt = 0; nt < 4; nt++)
#pragma unroll
            for (int c = 0; c < 4; c++) acc[mt][nt][c] = 0.f;

    const int nk = K >> 6;
    STAGE(0);
    asm volatile("cp.async.commit_group;");

    const int lane16 = lane & 15;
    const int lanehi = lane >> 4;
    const int brow_off = (lane & 7) + ((lane >> 4) << 3);
    const int bchi     = (lane >> 3) & 1;

    for (int kt = 0; kt < nk; kt++) {
        if (kt + 1 < nk) STAGE(kt + 1);
        asm volatile("cp.async.commit_group;");
        asm volatile("cp.async.wait_group 1;");
        __syncthreads();

        const uint32_t buf = sBase + ((kt & 1) ? STGB : 0);
        const uint32_t sAh = buf, sAl = buf + TEN, sBh = buf + 2*TEN, sBl = buf + 3*TEN;

#pragma unroll
        for (int ks = 0; ks < 4; ks++) {
            uint32_t ah[4][4], al[4][4], bh[4][2], bl[4][2];
#pragma unroll
            for (int mt = 0; mt < 4; mt++) {
                int row = wm + mt*16 + lane16;
                uint32_t off = (uint32_t)(row * 128 + (((ks*2 + lanehi) ^ (row & 7)) << 4));
                ldsm4(ah[mt], sAh + off);
                ldsm4(al[mt], sAl + off);
            }
#pragma unroll
            for (int np = 0; np < 2; np++) {
                int row = wn + np*16 + brow_off;
                uint32_t off = (uint32_t)(row * 128 + (((ks*2 + bchi) ^ (row & 7)) << 4));
                uint32_t r4[4];
                ldsm4(r4, sBh + off);
                bh[np*2][0] = r4[0]; bh[np*2][1] = r4[1];
                bh[np*2+1][0] = r4[2]; bh[np*2+1][1] = r4[3];
                ldsm4(r4, sBl + off);
                bl[np*2][0] = r4[0]; bl[np*2][1] = r4[1];
                bl[np*2+1][0] = r4[2]; bl[np*2+1][1] = r4[3];
            }
#pragma unroll
            for (int mt = 0; mt < 4; mt++)
#pragma unroll
                for (int nt = 0; nt < 4; nt++) {
                    mma_bf16(acc[mt][nt], ah[mt], bh[nt]);
                    mma_bf16(acc[mt][nt], ah[mt], bl[nt]);
                    mma_bf16(acc[mt][nt], al[mt], bh[nt]);
                }
        }
        __syncthreads();
    }
#undef STAGE

    const int g = lane >> 2;
    const int t = lane & 3;
#pragma unroll
    for (int mt = 0; mt < 4; mt++) {
        int r0 = mBase + wm + mt*16 + g;
#pragma unroll
        for (int nt = 0; nt < 4; nt++) {
            int c0 = nBase + wn + nt*8 + 2*t;
            float b0 = __ldg(bias + c0);
            float b1 = __ldg(bias + c0 + 1);
            float v00 = acc[mt][nt][0] + b0;
            float v01 = acc[mt][nt][1] + b1;
            float v10 = acc[mt][nt][2] + b0;
            float v11 = acc[mt][nt][3] + b1;
            if (epi == 0) {
                *(float2*)(Cf + (size_t)r0 * ldc + c0)       = make_float2(v00, v01);
                *(float2*)(Cf + (size_t)(r0 + 8) * ldc + c0) = make_float2(v10, v11);
            } else {
                v00 = 0.5f * v00 * (1.0f + erff(v00 * 0.70710678118654752f));
                v01 = 0.5f * v01 * (1.0f + erff(v01 * 0.70710678118654752f));
                v10 = 0.5f * v10 * (1.0f + erff(v10 * 0.70710678118654752f));
                v11 = 0.5f * v11 * (1.0f + erff(v11 * 0.70710678118654752f));
                __nv_bfloat16 h00 = __float2bfloat16(v00);
                __nv_bfloat16 h01 = __float2bfloat16(v01);
                __nv_bfloat16 h10 = __float2bfloat16(v10);
                __nv_bfloat16 h11 = __float2bfloat16(v11);
                __nv_bfloat162 hi0; hi0.x = h00; hi0.y = h01;
                __nv_bfloat162 hi1; hi1.x = h10; hi1.y = h11;
                __nv_bfloat162 lo0; lo0.x = __float2bfloat16(v00 - __bfloat162float(h00));
                                    lo0.y = __float2bfloat16(v01 - __bfloat162float(h01));
                __nv_bfloat162 lo1; lo1.x = __float2bfloat16(v10 - __bfloat162float(h10));
                                    lo1.y = __float2bfloat16(v11 - __bfloat162float(h11));
                *(__nv_bfloat162*)(Chi + (size_t)r0 * ldc + c0)       = hi0;
                *(__nv_bfloat162*)(Chi + (size_t)(r0 + 8) * ldc + c0) = hi1;
                *(__nv_bfloat162*)(Clo + (size_t)r0 * ldc + c0)       = lo0;
                *(__nv_bfloat162*)(Clo + (size_t)(r0 + 8) * ldc + c0) = lo1;
            }
        }
    }
}

// =====================================================================
// fp32->bf16 hi/lo split (weights)
// =====================================================================
__global__ void split_kernel(const float4* __restrict__ src,
                             uint2* __restrict__ hi, uint2* __restrict__ lo, int n4)
{
    int i = blockIdx.x * blockDim.x + threadIdx.x;
    if (i >= n4) return;
    float4 v = src[i];
    __nv_bfloat16 h[4], l[4];
    h[0] = __float2bfloat16(v.x); l[0] = __float2bfloat16(v.x - __bfloat162float(h[0]));
    h[1] = __float2bfloat16(v.y); l[1] = __float2bfloat16(v.y - __bfloat162float(h[1]));
    h[2] = __float2bfloat16(v.z); l[2] = __float2bfloat16(v.z - __bfloat162float(h[2]));
    h[3] = __float2bfloat16(v.w); l[3] = __float2bfloat16(v.w - __bfloat162float(h[3]));
    hi[i] = *(uint2*)h;
    lo[i] = *(uint2*)l;
}

// =====================================================================
// fp32 tiled SGEMM (session alignment only)
// =====================================================================
#define BM 128
#define BN 64
#define BK 16

__global__ __launch_bounds__(256) void sgemm_kernel(
    const float* __restrict__ A, int lda,
    const float* __restrict__ Bm, int ldb,
    const float* __restrict__ bias,
    float* __restrict__ C, int ldc,
    int M, int N, int K,
    const int* __restrict__ sidx,
    size_t strideAb, size_t strideCb, size_t strideBsel, size_t strideBiasSel)
{
    __shared__ __align__(16) float As[BK][BM + 4];
    __shared__ __align__(16) float Bs[BK][BN + 4];

    if (sidx) {
        int bz = blockIdx.z;
        A    += (size_t)bz * strideAb;
        C    += (size_t)bz * strideCb;
        int s = __ldg(&sidx[bz]);
        Bm   += (size_t)s * strideBsel;
        bias += (size_t)s * strideBiasSel;
    }

    const int tid   = threadIdx.x;
    const int mBase = blockIdx.y * BM;
    const int nBase = blockIdx.x * BN;
    const int tm    = (tid / 16) * 8;
    const int tn    = (tid % 16) * 4;

    float acc[8][4];
#pragma unroll
    for (int i = 0; i < 8; i++)
#pragma unroll
        for (int j = 0; j < 4; j++) acc[i][j] = 0.f;

    for (int k0 = 0; k0 < K; k0 += BK) {
#pragma unroll
        for (int it = 0; it < 2; it++) {
            int l  = tid + it * 256;
            int m  = l >> 2;
            int kq = (l & 3) * 4;
            float4 v = *(const float4*)(A + (size_t)(mBase + m) * lda + k0 + kq);
            As[kq + 0][m] = v.x; As[kq + 1][m] = v.y;
            As[kq + 2][m] = v.z; As[kq + 3][m] = v.w;
        }
        {
            int l  = tid;
            int n  = l >> 2;
            int kq = (l & 3) * 4;
            float4 v = *(const float4*)(Bm + (size_t)(nBase + n) * ldb + k0 + kq);
            Bs[kq + 0][n] = v.x; Bs[kq + 1][n] = v.y;
            Bs[kq + 2][n] = v.z; Bs[kq + 3][n] = v.w;
        }
        __syncthreads();

#pragma unroll
        for (int kk = 0; kk < BK; kk++) {
            float4 a0 = *(const float4*)&As[kk][tm];
            float4 a1 = *(const float4*)&As[kk][tm + 4];
            float4 b0 = *(const float4*)&Bs[kk][tn];
            float av[8] = {a0.x, a0.y, a0.z, a0.w, a1.x, a1.y, a1.z, a1.w};
            float bv[4] = {b0.x, b0.y, b0.z, b0.w};
#pragma unroll
            for (int i = 0; i < 8; i++)
#pragma unroll
                for (int j = 0; j < 4; j++) acc[i][j] += av[i] * bv[j];
        }
        __syncthreads();
    }

    float bb[4];
#pragma unroll
    for (int j = 0; j < 4; j++) bb[j] = bias[nBase + tn + j];

#pragma unroll
    for (int i = 0; i < 8; i++) {
        *(float4*)(C + (size_t)(mBase + tm + i) * ldc + nBase + tn) =
            make_float4(acc[i][0] + bb[0], acc[i][1] + bb[1],
                        acc[i][2] + bb[2], acc[i][3] + bb[3]);
    }
}

// =====================================================================
// tokens gather + bf16 hi/lo split fused
// =====================================================================
__global__ void tokens_split_kernel(float* __restrict__ out_tokens,
                                    __nv_bfloat16* __restrict__ tokHi,
                                    __nv_bfloat16* __restrict__ tokLo)
{
    int idx = blockIdx.x * blockDim.x + threadIdx.x;
    if (idx >= MROWS * TOK_) return;
    int t   = idx % TOK_;
    int row = idx / TOK_;
    int n   = row % N_;
    int b   = row / N_;
    int d   = t / P_;
    int p   = t % P_;
    float v = g_aligned[((size_t)(b * T_ + n + p)) * D_ + d];
    out_tokens[idx] = v;
    __nv_bfloat16 h = __float2bfloat16(v);
    tokHi[idx] = h;
    tokLo[idx] = __float2bfloat16(v - __bfloat162float(h));
}

// =====================================================================
// RMS norm + bf16 hi/lo split fused
// =====================================================================
__global__ __launch_bounds__(128) void rms_split_kernel(
    const float* __restrict__ scale,
    __nv_bfloat16* __restrict__ hHi, __nv_bfloat16* __restrict__ hLo)
{
    int row = blockIdx.x;
    const float* h = g_h + (size_t)row * H_;
    int tid = threadIdx.x;

    float4 x = *(const float4*)(h + tid * 4);
    float ss = x.x * x.x + x.y * x.y + x.z * x.z + x.w * x.w;
#pragma unroll
    for (int o = 16; o; o >>= 1) ss += __shfl_xor_sync(0xffffffffu, ss, o);

    __shared__ float wsum[4];
    if ((tid & 31) == 0) wsum[tid >> 5] = ss;
    __syncthreads();
    float tot = wsum[0] + wsum[1] + wsum[2] + wsum[3];
    float inv = rsqrtf(tot * (1.0f / H_) + 1e-6f);

    float4 sc = *(const float4*)(scale + tid * 4);
    float v[4] = { x.x * inv * sc.x, x.y * inv * sc.y,
                   x.z * inv * sc.z, x.w * inv * sc.w };
    __nv_bfloat16 hi[4], lo[4];
#pragma unroll
    for (int j = 0; j < 4; j++) {
        hi[j] = __float2bfloat16(v[j]);
        lo[j] = __float2bfloat16(v[j] - __bfloat162float(hi[j]));
    }
    *(uint2*)(hHi + (size_t)row * H_ + tid * 4) = *(uint2*)hi;
    *(uint2*)(hLo + (size_t)row * H_ + tid * 4) = *(uint2*)lo;
}

// =====================================================================
// GRU v5 (tensor-core): 128 blocks = 32 col-groups x 4 batch-groups.
// State bf16 hi/lo. Per step: stage 16-batch h slice into bgemm-format
// swizzled tiles; 8 warps each own a 64-wide K slice and run the proven
// m16n8k16 bf16-split fragment path (M=16 batches, N=48 gate cols);
// cross-warp K-reduce in smem; 1 output/thread gate math.
// Barrier: proven group-scoped atomic counter (R7/R14).
// =====================================================================
#define GRU_BLOCKS 128
// smem byte offsets
#define GS_WHI 0                          // 8 chunks * 48 rows * 128B = 49152
#define GS_WLO 49152
#define GS_HHI 98304                      // 8 chunks * 16 rows * 128B = 16384
#define GS_HLO 114688
#define GS_RED 131072                     // 8 warps * 768 fp32 = 24576
#define GS_BHH 155648                     // 48 fp32
#define GRU_DSMEM (155648 + 192)

__global__ void gru_init_kernel()
{
    int idx = blockIdx.x * blockDim.x + threadIdx.x;
    __nv_bfloat16* ph = &g_hsHi[0][0][0];
    __nv_bfloat16* pl = &g_hsLo[0][0][0];
    if (idx < 2 * B_ * H_) { ph[idx] = __float2bfloat16(0.f); pl[idx] = __float2bfloat16(0.f); }
    if (idx < 4*32) g_gctr[idx] = 0u;
}

__device__ __forceinline__ void gbar_group(unsigned* ctr, unsigned target)
{
    __threadfence();
    __syncthreads();
    if (threadIdx.x == 0) {
        atomicAdd(ctr, 1u);
        unsigned v;
        do {
            asm volatile("ld.acquire.gpu.u32 %0, [%1];" : "=r"(v) : "l"(ctr));
        } while (v < target);
    }
    __syncthreads();
}

__global__ __launch_bounds__(256, 1) void gru_kernel(
    const __nv_bfloat16* __restrict__ whhHi, const __nv_bfloat16* __restrict__ whhLo,
    const float* __restrict__ bhh,
    __nv_bfloat16* __restrict__ hidHi, __nv_bfloat16* __restrict__ hidLo)
{
    extern __shared__ char gsm[];
    const uint32_t sB = smem_u32(gsm);
    float* red  = (float*)(gsm + GS_RED);
    float* sbhh = (float*)(gsm + GS_BHH);

    const int bid  = blockIdx.x;
    const int cg   = bid >> 2;        // col-group 0..31
    const int bg   = bid & 3;         // batch-group 0..3
    const int tid  = threadIdx.x;
    const int warp = tid >> 5;
    const int lane = tid & 31;
    const int col0 = cg * 16;
    unsigned* myctr = &g_gctr[bg * 32];

    // ---- one-time: weights (48 rows = [r|z|n] x 16 cols) into swizzled tiles
    // row r (0..47): gate g=r>>4, col c=r&15 -> global row g*H_+col0+c
    for (int idx = tid; idx < 48 * H_; idx += 256) {
        int k = idx & (H_ - 1);
        int r = idx >> 9;
        int g = r >> 4, c = r & 15;
        size_t gidx = (size_t)(g * H_ + col0 + c) * H_ + k;
        int kc = k >> 6, cc = (k >> 3) & 7, off = k & 7;
        uint32_t so = (uint32_t)(kc * 6144 + r * 128 + ((cc ^ (r & 7)) << 4) + off * 2);
        *(__nv_bfloat16*)(gsm + GS_WHI + so) = whhHi[gidx];
        *(__nv_bfloat16*)(gsm + GS_WLO + so) = whhLo[gidx];
    }
    if (tid < 48) {
        int g = tid >> 4, c = tid & 15;
        sbhh[tid] = bhh[g * H_ + col0 + c];
    }
    __syncthreads();

    const int lane16 = lane & 15;
    const int lanehi = lane >> 4;
    const int brow_off = (lane & 7) + ((lane >> 4) << 3);
    const int bchi     = (lane >> 3) & 1;
    const int g  = lane >> 2;
    const int t  = lane & 3;

    const int b_out  = tid >> 4;      // 0..15 (output batch)
    const int hc     = tid & 15;      // output hidden col (local)
    const int gbo    = bg * 16 + b_out;
    const int ocol   = col0 + hc;
    // hp smem address for (b_out, ocol)
    const int hk = ocol;
    const uint32_t hpOff = (uint32_t)((hk >> 6) * 2048 + b_out * 128 +
                           ((((hk >> 3) & 7) ^ (b_out & 7)) << 4) + (hk & 7) * 2);

    int cur = 0;
    for (int n = 0; n < N_; n++) {
        // ---- stage 16-batch h slice (hi+lo, 32KB) into swizzled tiles
#pragma unroll
        for (int q = 0; q < 8; q++) {
            int id  = tid * 8 + q;              // 0..2047
            int ten = id >> 10;                 // 0 hi, 1 lo
            int rem = id & 1023;
            int r   = rem >> 6;                 // batch row 0..15
            int cu  = rem & 63;                 // 16B unit in row
            int kc  = cu >> 3, cc = cu & 7;
            uint32_t dst = sB + (ten ? GS_HLO : GS_HHI)
                         + (uint32_t)(kc * 2048 + r * 128 + ((cc ^ (r & 7)) << 4));
            const __nv_bfloat16* src = ten
                ? &g_hsLo[cur][bg*16 + r][kc*64 + cc*8]
                : &g_hsHi[cur][bg*16 + r][kc*64 + cc*8];
            asm volatile("cp.async.cg.shared.global [%0], [%1], 16;"
                         :: "r"(dst), "l"(src));
        }
        asm volatile("cp.async.commit_group;");

        // gx prefetch (overlaps staging)
        const float* gx = g_gx + ((size_t)(gbo * N_ + n)) * H3;
        float gxr = __ldg(gx + ocol);
        float gxz = __ldg(gx + H_ + ocol);
        float gxn = __ldg(gx + 2*H_ + ocol);

        asm volatile("cp.async.wait_group 0;");
        __syncthreads();

        // ---- warp w: K slice [w*64, w*64+64), M=16, N=48 (6 n-tiles)
        float acc[6][4];
#pragma unroll
        for (int nt = 0; nt < 6; nt++)
#pragma unroll
            for (int c = 0; c < 4; c++) acc[nt][c] = 0.f;

        const uint32_t hHiB = sB + GS_HHI + warp * 2048;
        const uint32_t hLoB = sB + GS_HLO + warp * 2048;
        const uint32_t wHiB = sB + GS_WHI + warp * 6144;
        const uint32_t wLoB = sB + GS_WLO + warp * 6144;

#pragma unroll
        for (int ks = 0; ks < 4; ks++) {
            uint32_t ah[4], al[4];
            {
                int row = lane16;
                uint32_t off = (uint32_t)(row * 128 + (((ks*2 + lanehi) ^ (row & 7)) << 4));
                ldsm4(ah, hHiB + off);
                ldsm4(al, hLoB + off);
            }
#pragma unroll
            for (int np = 0; np < 3; np++) {
                int row = np*16 + brow_off;
                uint32_t off = (uint32_t)(row * 128 + (((ks*2 + bchi) ^ (row & 7)) << 4));
                uint32_t r4[4];
                uint32_t bh0[2], bh1[2], bl0[2], bl1[2];
                ldsm4(r4, wHiB + off);
                bh0[0] = r4[0]; bh0[1] = r4[1];
                bh1[0] = r4[2]; bh1[1] = r4[3];
                ldsm4(r4, wLoB + off);
                bl0[0] = r4[0]; bl0[1] = r4[1];
                bl1[0] = r4[2]; bl1[1] = r4[3];
                mma_bf16(acc[2*np],     ah, bh0);
                mma_bf16(acc[2*np],     ah, bl0);
                mma_bf16(acc[2*np],     al, bh0);
                mma_bf16(acc[2*np + 1], ah, bh1);
                mma_bf16(acc[2*np + 1], ah, bl1);
                mma_bf16(acc[2*np + 1], al, bh1);
            }
        }

        // ---- store per-warp partials: red[warp][row*48 + col]
        {
            float* rw = red + warp * 768;
#pragma unroll
            for (int nt = 0; nt < 6; nt++) {
                int c0 = nt*8 + 2*t;
                *(float2*)(rw + g * 48 + c0)       = make_float2(acc[nt][0], acc[nt][1]);
                *(float2*)(rw + (g + 8) * 48 + c0) = make_float2(acc[nt][2], acc[nt][3]);
            }
        }
        // hp read (from staged smem): hi + lo
        float hp;
        {
            __nv_bfloat16 phi = *(__nv_bfloat16*)(gsm + GS_HHI + hpOff);
            __nv_bfloat16 plo = *(__nv_bfloat16*)(gsm + GS_HLO + hpOff);
            hp = __bfloat162float(phi) + __bfloat162float(plo);
        }
        __syncthreads();

        // ---- reduce 8 warps, gate math, one output per thread
        float s0 = 0.f, s1 = 0.f, s2 = 0.f;
#pragma unroll
        for (int w = 0; w < 8; w++) {
            const float* rw = red + w * 768 + b_out * 48;
            s0 += rw[hc];
            s1 += rw[16 + hc];
            s2 += rw[32 + hc];
        }
        float r  = 1.0f / (1.0f + expf(-(gxr + s0 + sbhh[hc])));
        float z  = 1.0f / (1.0f + expf(-(gxz + s1 + sbhh[16 + hc])));
        float nn = tanhf(gxn + r * (s2 + sbhh[32 + hc]));
        float hn = (1.0f - z) * nn + z * hp;

        __nv_bfloat16 oh = __float2bfloat16(hn);
        __nv_bfloat16 ol = __float2bfloat16(hn - __bfloat162float(oh));
        g_hsHi[cur ^ 1][gbo][ocol] = oh;
        g_hsLo[cur ^ 1][gbo][ocol] = ol;
        size_t base = ((size_t)(gbo * N_ + n)) * H_ + ocol;
        hidHi[base] = oh;
        hidLo[base] = ol;

        gbar_group(myctr, (unsigned)(n + 1) * 32u);
        cur ^= 1;
    }
}

// =====================================================================
// host side
// =====================================================================
#define BG_DSMEM  (2 * STGB)   // 131072 B

static void launch_split(const float* src, __nv_bfloat16* hi, __nv_bfloat16* lo, size_t n)
{
    int n4 = (int)(n / 4);
    split_kernel<<<(n4 + 255) / 256, 256>>>((const float4*)src, (uint2*)hi, (uint2*)lo, n4);
}

extern "C" void kernel_launch(void* const* d_in, const int* in_sizes, int n_in,
                              void* d_out, int out_size)
{
    const float* x      = (const float*)d_in[0];
    const int*   sidx   = (const int*)  d_in[1];
    const float* sW     = (const float*)d_in[2];
    const float* sb     = (const float*)d_in[3];
    const float* projW  = (const float*)d_in[4];
    const float* projb  = (const float*)d_in[5];
    const float* rscale = (const float*)d_in[6];
    const float* Wih    = (const float*)d_in[7];
    const float* Whh    = (const float*)d_in[8];
    const float* bih    = (const float*)d_in[9];
    const float* bhh    = (const float*)d_in[10];
    const float* W1     = (const float*)d_in[11];
    const float* b1     = (const float*)d_in[12];
    const float* W2     = (const float*)d_in[13];
    const float* b2     = (const float*)d_in[14];

    float* out        = (float*)d_out;
    float* out_preds  = out;
    float* out_tokens = out + (size_t)K_H * MROWS * TOK_;

    float *pAligned, *pH, *pGx;
    cudaGetSymbolAddress((void**)&pAligned, g_aligned);
    cudaGetSymbolAddress((void**)&pH,       g_h);
    cudaGetSymbolAddress((void**)&pGx,      g_gx);

    __nv_bfloat16 *tokHi, *tokLo, *hHi, *hLo, *hidHi, *hidLo, *actHi, *actLo;
    __nv_bfloat16 *pwHi, *pwLo, *wihHi, *wihLo, *whhHi, *whhLo, *w1Hi, *w1Lo, *w2Hi, *w2Lo;
    cudaGetSymbolAddress((void**)&tokHi, g_tokHi); cudaGetSymbolAddress((void**)&tokLo, g_tokLo);
    cudaGetSymbolAddress((void**)&hHi,   g_hHi);   cudaGetSymbolAddress((void**)&hLo,   g_hLo);
    cudaGetSymbolAddress((void**)&hidHi, g_hidHi); cudaGetSymbolAddress((void**)&hidLo, g_hidLo);
    cudaGetSymbolAddress((void**)&actHi, g_actHi); cudaGetSymbolAddress((void**)&actLo, g_actLo);
    cudaGetSymbolAddress((void**)&pwHi,  g_pwHi);  cudaGetSymbolAddress((void**)&pwLo,  g_pwLo);
    cudaGetSymbolAddress((void**)&wihHi, g_wihHi); cudaGetSymbolAddress((void**)&wihLo, g_wihLo);
    cudaGetSymbolAddress((void**)&whhHi, g_whhHi); cudaGetSymbolAddress((void**)&whhLo, g_whhLo);
    cudaGetSymbolAddress((void**)&w1Hi,  g_w1Hi);  cudaGetSymbolAddress((void**)&w1Lo,  g_w1Lo);
    cudaGetSymbolAddress((void**)&w2Hi,  g_w2Hi);  cudaGetSymbolAddress((void**)&w2Lo,  g_w2Lo);

    static int attr_set = 0;
    if (!attr_set) {
        cudaFuncSetAttribute(bgemm_kernel,
                             cudaFuncAttributeMaxDynamicSharedMemorySize, BG_DSMEM);
        cudaFuncSetAttribute(gru_kernel,
                             cudaFuncAttributeMaxDynamicSharedMemorySize, GRU_DSMEM);
        attr_set = 1;
    }

    // 0) proj weight split
    launch_split(projW, pwHi, pwLo, (size_t)H_ * TOK_);

    // 1) session alignment (fp32 — feeds tokens output)
    sgemm_kernel<<<dim3(D_ / BN, T_ / BM, B_), 256>>>(
        x, D_, sW, D_, sb, pAligned, D_,
        T_, D_, D_,
        sidx, (size_t)T_ * D_, (size_t)T_ * D_, (size_t)D_ * D_, (size_t)D_);

    // 2) tokens gather + split (fused)
    tokens_split_kernel<<<(MROWS * TOK_ + 255) / 256, 256>>>(out_tokens, tokHi, tokLo);

    // 3) proj GEMM
    bgemm_kernel<<<dim3(H_ / 128, MROWS / 128), 256, BG_DSMEM>>>(
        tokHi, tokLo, TOK_, pwHi, pwLo, TOK_, projb,
        pH, nullptr, nullptr, H_, TOK_, 0);

    // 4) RMS + split (fused)
    rms_split_kernel<<<MROWS, 128>>>(rscale, hHi, hLo);

    // 5) Wih + Whh splits
    launch_split(Wih, wihHi, wihLo, (size_t)H3 * H_);
    launch_split(Whh, whhHi, whhLo, (size_t)H3 * H_);

    // 6) gx = h @ Wih^T + bih
    bgemm_kernel<<<dim3(H3 / 128, MROWS / 128), 256, BG_DSMEM>>>(
        hHi, hLo, H_, wihHi, wihLo, H_, bih,
        pGx, nullptr, nullptr, H3, H_, 0);

    launch_split(W1, w1Hi, w1Lo, (size_t)H3 * H_);
    launch_split(W2, w2Hi, w2Lo, (size_t)K_H * TOK_ * H_);

    // 7) GRU recurrence (tensor-core step; bf16 hi/lo hidden out)
    gru_init_kernel<<<(2 * B_ * H_ + 255) / 256, 256>>>();
    gru_kernel<<<GRU_BLOCKS, 256, GRU_DSMEM>>>(whhHi, whhLo, bhh, hidHi, hidLo);

    // 8) head1 (3 horizons fused, N=1536) + exact GELU -> bf16 hi/lo
    bgemm_kernel<<<dim3(H3 / 128, MROWS / 128), 256, BG_DSMEM>>>(
        hidHi, hidLo, H_, w1Hi, w1Lo, H_, b1,
        nullptr, actHi, actLo, H3, H_, 1);

    // 9) head2 per horizon -> preds
    for (int k = 0; k < K_H; k++) {
        bgemm_kernel<<<dim3(TOK_ / 128, MROWS / 128), 256, BG_DSMEM>>>(
            actHi + (size_t)k * H_, actLo + (size_t)k * H_, H3,
            w2Hi + (size_t)k * TOK_ * H_, w2Lo + (size_t)k * TOK_ * H_, H_,
            b2 + (size_t)k * TOK_,
            out_preds + (size_t)k * MROWS * TOK_, nullptr, nullptr, TOK_, H_, 0);
    }
}

// round 16
// speedup vs baseline: 2.1982x; 1.0330x over previous
#include <cuda_runtime.h>
#include <cuda_bf16.h>
#include <math.h>
#include <stdint.h>

// ---------------- problem constants ----------------
#define B_   64
#define T_   512
#define D_   128
#define P_   3
#define H_   512
#define K_H  3
#define TOK_ 384
#define N_   510
#define MROWS (B_*N_)          // 32640
#define H3   (3*H_)            // 1536

// ---------------- device scratch ----------------
__device__ float g_aligned[B_*T_*D_];
__device__ float g_h[(size_t)MROWS*H_];
__device__ float g_gx[(size_t)MROWS*H3];
__device__ __nv_bfloat16 g_hsHi[2][B_][H_];   // GRU state bf16 hi, double buffered
__device__ __nv_bfloat16 g_hsLo[2][B_][H_];   // GRU state bf16 lo
__device__ unsigned g_gctr[4*32];             // one counter per batch-group, 128B apart

// bf16 hi/lo split buffers
__device__ __nv_bfloat16 g_tokHi[(size_t)MROWS*TOK_];
__device__ __nv_bfloat16 g_tokLo[(size_t)MROWS*TOK_];
__device__ __nv_bfloat16 g_hHi[(size_t)MROWS*H_];
__device__ __nv_bfloat16 g_hLo[(size_t)MROWS*H_];
__device__ __nv_bfloat16 g_hidHi[(size_t)MROWS*H_];
__device__ __nv_bfloat16 g_hidLo[(size_t)MROWS*H_];
__device__ __nv_bfloat16 g_actHi[(size_t)MROWS*H3];
__device__ __nv_bfloat16 g_actLo[(size_t)MROWS*H3];
__device__ __nv_bfloat16 g_pwHi[H_*TOK_],  g_pwLo[H_*TOK_];
__device__ __nv_bfloat16 g_wihHi[H3*H_],   g_wihLo[H3*H_];
__device__ __nv_bfloat16 g_whhHi[H3*H_],   g_whhLo[H3*H_];
__device__ __nv_bfloat16 g_w1Hi[H3*H_],    g_w1Lo[H3*H_];
__device__ __nv_bfloat16 g_w2Hi[K_H*TOK_*H_], g_w2Lo[K_H*TOK_*H_];

// =====================================================================
// helpers
// =====================================================================
__device__ __forceinline__ uint32_t smem_u32(const void* p)
{
    uint32_t a;
    asm("{ .reg .u64 t; cvta.to.shared.u64 t, %1; cvt.u32.u64 %0, t; }"
        : "=r"(a) : "l"(p));
    return a;
}

__device__ __forceinline__ void ldsm4(uint32_t* r, uint32_t addr)
{
    asm volatile("ldmatrix.sync.aligned.m8n8.x4.shared.b16 {%0,%1,%2,%3}, [%4];"
                 : "=r"(r[0]), "=r"(r[1]), "=r"(r[2]), "=r"(r[3]) : "r"(addr));
}

__device__ __forceinline__ void mma_bf16(float* c, const uint32_t* a, const uint32_t* b)
{
    asm volatile(
        "mma.sync.aligned.m16n8k16.row.col.f32.bf16.bf16.f32 "
        "{%0,%1,%2,%3}, {%4,%5,%6,%7}, {%8,%9}, {%0,%1,%2,%3};"
        : "+f"(c[0]), "+f"(c[1]), "+f"(c[2]), "+f"(c[3])
        : "r"(a[0]), "r"(a[1]), "r"(a[2]), "r"(a[3]), "r"(b[0]), "r"(b[1]));
}

// MUFU-backed gate math (sm_75+ ISA, serial-path cheap)
__device__ __forceinline__ float sigmoid_fast(float x)
{
    float e;
    asm("ex2.approx.f32 %0, %1;" : "=f"(e) : "f"(-1.4426950408889634f * x));
    float r;
    asm("rcp.approx.f32 %0, %1;" : "=f"(r) : "f"(1.0f + e));
    return r;
}
__device__ __forceinline__ float tanh_fast(float x)
{
    float r;
    asm("tanh.approx.f32 %0, %1;" : "=f"(r) : "f"(x));
    return r;
}

// =====================================================================
// bf16 split-precision warp-MMA GEMM (unchanged — proven, 59% tensor)
// =====================================================================
#define TEN  16384
#define STGB (4*TEN)

__global__ __launch_bounds__(256) void bgemm_kernel(
    const __nv_bfloat16* __restrict__ Ahi, const __nv_bfloat16* __restrict__ Alo, int lda,
    const __nv_bfloat16* __restrict__ Bhi, const __nv_bfloat16* __restrict__ Blo, int ldb,
    const float* __restrict__ bias,
    float* __restrict__ Cf,
    __nv_bfloat16* __restrict__ Chi, __nv_bfloat16* __restrict__ Clo,
    int ldc, int K, int epi)
{
    extern __shared__ char dsm[];
    const uint32_t sBase = smem_u32(dsm);

    const int tid  = threadIdx.x;
    const int warp = tid >> 5;
    const int lane = tid & 31;
    const int mBase = blockIdx.y << 7;
    const int nBase = blockIdx.x << 7;
    const int wm = (warp & 1) << 6;
    const int wn = (warp >> 1) << 5;

    const int ten   = tid >> 6;
    const __nv_bfloat16* tp = (ten == 0) ? Ahi : (ten == 1) ? Alo : (ten == 2) ? Bhi : Blo;
    const int ldt   = (ten < 2) ? lda : ldb;
    const int rbase = (ten < 2) ? mBase : nBase;
    const int lsub  = tid & 63;

#define STAGE(kt) do {                                                         \
    uint32_t sdst = sBase + (((kt) & 1) ? STGB : 0) + ten * TEN;               \
    const __nv_bfloat16* gsrc = tp + (size_t)rbase * ldt + ((kt) << 6);        \
    _Pragma("unroll")                                                          \
    for (int q_ = 0; q_ < 16; q_++) {                                          \
        int id_  = lsub + (q_ << 6);                                           \
        int row_ = id_ >> 3;                                                   \
        int cc_  = id_ & 7;                                                    \
        uint32_t d_ = sdst + row_ * 128 + ((cc_ ^ (row_ & 7)) << 4);           \
        const __nv_bfloat16* s_ = gsrc + (size_t)row_ * ldt + (cc_ << 3);      \
        asm volatile("cp.async.cg.shared.global [%0], [%1], 16;"               \
                     :: "r"(d_), "l"(s_));                                     \
    }                                                                          \
} while (0)

    float acc[4][4][4];
#pragma unroll
    for (int mt = 0; mt < 4; mt++)
#pragma unroll
        for (int nt = 0; nt < 4; nt++)
#pragma unroll
            for (int c = 0; c < 4; c++) acc[mt][nt][c] = 0.f;

    const int nk = K >> 6;
    STAGE(0);
    asm volatile("cp.async.commit_group;");

    const int lane16 = lane & 15;
    const int lanehi = lane >> 4;
    const int brow_off = (lane & 7) + ((lane >> 4) << 3);
    const int bchi     = (lane >> 3) & 1;

    for (int kt = 0; kt < nk; kt++) {
        if (kt + 1 < nk) STAGE(kt + 1);
        asm volatile("cp.async.commit_group;");
        asm volatile("cp.async.wait_group 1;");
        __syncthreads();

        const uint32_t buf = sBase + ((kt & 1) ? STGB : 0);
        const uint32_t sAh = buf, sAl = buf + TEN, sBh = buf + 2*TEN, sBl = buf + 3*TEN;

#pragma unroll
        for (int ks = 0; ks < 4; ks++) {
            uint32_t ah[4][4], al[4][4], bh[4][2], bl[4][2];
#pragma unroll
            for (int mt = 0; mt < 4; mt++) {
                int row = wm + mt*16 + lane16;
                uint32_t off = (uint32_t)(row * 128 + (((ks*2 + lanehi) ^ (row & 7)) << 4));
                ldsm4(ah[mt], sAh + off);
                ldsm4(al[mt], sAl + off);
            }
#pragma unroll
            for (int np = 0; np < 2; np++) {
                int row = wn + np*16 + brow_off;
                uint32_t off = (uint32_t)(row * 128 + (((ks*2 + bchi) ^ (row & 7)) << 4));
                uint32_t r4[4];
                ldsm4(r4, sBh + off);
                bh[np*2][0] = r4[0]; bh[np*2][1] = r4[1];
                bh[np*2+1][0] = r4[2]; bh[np*2+1][1] = r4[3];
                ldsm4(r4, sBl + off);
                bl[np*2][0] = r4[0]; bl[np*2][1] = r4[1];
                bl[np*2+1][0] = r4[2]; bl[np*2+1][1] = r4[3];
            }
#pragma unroll
            for (int mt = 0; mt < 4; mt++)
#pragma unroll
                for (int nt = 0; nt < 4; nt++) {
                    mma_bf16(acc[mt][nt], ah[mt], bh[nt]);
                    mma_bf16(acc[mt][nt], ah[mt], bl[nt]);
                    mma_bf16(acc[mt][nt], al[mt], bh[nt]);
                }
        }
        __syncthreads();
    }
#undef STAGE

    const int g = lane >> 2;
    const int t = lane & 3;
#pragma unroll
    for (int mt = 0; mt < 4; mt++) {
        int r0 = mBase + wm + mt*16 + g;
#pragma unroll
        for (int nt = 0; nt < 4; nt++) {
            int c0 = nBase + wn + nt*8 + 2*t;
            float b0 = __ldg(bias + c0);
            float b1 = __ldg(bias + c0 + 1);
            float v00 = acc[mt][nt][0] + b0;
            float v01 = acc[mt][nt][1] + b1;
            float v10 = acc[mt][nt][2] + b0;
            float v11 = acc[mt][nt][3] + b1;
            if (epi == 0) {
                *(float2*)(Cf + (size_t)r0 * ldc + c0)       = make_float2(v00, v01);
                *(float2*)(Cf + (size_t)(r0 + 8) * ldc + c0) = make_float2(v10, v11);
            } else {
                v00 = 0.5f * v00 * (1.0f + erff(v00 * 0.70710678118654752f));
                v01 = 0.5f * v01 * (1.0f + erff(v01 * 0.70710678118654752f));
                v10 = 0.5f * v10 * (1.0f + erff(v10 * 0.70710678118654752f));
                v11 = 0.5f * v11 * (1.0f + erff(v11 * 0.70710678118654752f));
                __nv_bfloat16 h00 = __float2bfloat16(v00);
                __nv_bfloat16 h01 = __float2bfloat16(v01);
                __nv_bfloat16 h10 = __float2bfloat16(v10);
                __nv_bfloat16 h11 = __float2bfloat16(v11);
                __nv_bfloat162 hi0; hi0.x = h00; hi0.y = h01;
                __nv_bfloat162 hi1; hi1.x = h10; hi1.y = h11;
                __nv_bfloat162 lo0; lo0.x = __float2bfloat16(v00 - __bfloat162float(h00));
                                    lo0.y = __float2bfloat16(v01 - __bfloat162float(h01));
                __nv_bfloat162 lo1; lo1.x = __float2bfloat16(v10 - __bfloat162float(h10));
                                    lo1.y = __float2bfloat16(v11 - __bfloat162float(h11));
                *(__nv_bfloat162*)(Chi + (size_t)r0 * ldc + c0)       = hi0;
                *(__nv_bfloat162*)(Chi + (size_t)(r0 + 8) * ldc + c0) = hi1;
                *(__nv_bfloat162*)(Clo + (size_t)r0 * ldc + c0)       = lo0;
                *(__nv_bfloat162*)(Clo + (size_t)(r0 + 8) * ldc + c0) = lo1;
            }
        }
    }
}

// =====================================================================
// fp32->bf16 hi/lo split (weights)
// =====================================================================
__global__ void split_kernel(const float4* __restrict__ src,
                             uint2* __restrict__ hi, uint2* __restrict__ lo, int n4)
{
    int i = blockIdx.x * blockDim.x + threadIdx.x;
    if (i >= n4) return;
    float4 v = src[i];
    __nv_bfloat16 h[4], l[4];
    h[0] = __float2bfloat16(v.x); l[0] = __float2bfloat16(v.x - __bfloat162float(h[0]));
    h[1] = __float2bfloat16(v.y); l[1] = __float2bfloat16(v.y - __bfloat162float(h[1]));
    h[2] = __float2bfloat16(v.z); l[2] = __float2bfloat16(v.z - __bfloat162float(h[2]));
    h[3] = __float2bfloat16(v.w); l[3] = __float2bfloat16(v.w - __bfloat162float(h[3]));
    hi[i] = *(uint2*)h;
    lo[i] = *(uint2*)l;
}

// =====================================================================
// fp32 tiled SGEMM (session alignment only)
// =====================================================================
#define BM 128
#define BN 64
#define BK 16

__global__ __launch_bounds__(256) void sgemm_kernel(
    const float* __restrict__ A, int lda,
    const float* __restrict__ Bm, int ldb,
    const float* __restrict__ bias,
    float* __restrict__ C, int ldc,
    int M, int N, int K,
    const int* __restrict__ sidx,
    size_t strideAb, size_t strideCb, size_t strideBsel, size_t strideBiasSel)
{
    __shared__ __align__(16) float As[BK][BM + 4];
    __shared__ __align__(16) float Bs[BK][BN + 4];

    if (sidx) {
        int bz = blockIdx.z;
        A    += (size_t)bz * strideAb;
        C    += (size_t)bz * strideCb;
        int s = __ldg(&sidx[bz]);
        Bm   += (size_t)s * strideBsel;
        bias += (size_t)s * strideBiasSel;
    }

    const int tid   = threadIdx.x;
    const int mBase = blockIdx.y * BM;
    const int nBase = blockIdx.x * BN;
    const int tm    = (tid / 16) * 8;
    const int tn    = (tid % 16) * 4;

    float acc[8][4];
#pragma unroll
    for (int i = 0; i < 8; i++)
#pragma unroll
        for (int j = 0; j < 4; j++) acc[i][j] = 0.f;

    for (int k0 = 0; k0 < K; k0 += BK) {
#pragma unroll
        for (int it = 0; it < 2; it++) {
            int l  = tid + it * 256;
            int m  = l >> 2;
            int kq = (l & 3) * 4;
            float4 v = *(const float4*)(A + (size_t)(mBase + m) * lda + k0 + kq);
            As[kq + 0][m] = v.x; As[kq + 1][m] = v.y;
            As[kq + 2][m] = v.z; As[kq + 3][m] = v.w;
        }
        {
            int l  = tid;
            int n  = l >> 2;
            int kq = (l & 3) * 4;
            float4 v = *(const float4*)(Bm + (size_t)(nBase + n) * ldb + k0 + kq);
            Bs[kq + 0][n] = v.x; Bs[kq + 1][n] = v.y;
            Bs[kq + 2][n] = v.z; Bs[kq + 3][n] = v.w;
        }
        __syncthreads();

#pragma unroll
        for (int kk = 0; kk < BK; kk++) {
            float4 a0 = *(const float4*)&As[kk][tm];
            float4 a1 = *(const float4*)&As[kk][tm + 4];
            float4 b0 = *(const float4*)&Bs[kk][tn];
            float av[8] = {a0.x, a0.y, a0.z, a0.w, a1.x, a1.y, a1.z, a1.w};
            float bv[4] = {b0.x, b0.y, b0.z, b0.w};
#pragma unroll
            for (int i = 0; i < 8; i++)
#pragma unroll
                for (int j = 0; j < 4; j++) acc[i][j] += av[i] * bv[j];
        }
        __syncthreads();
    }

    float bb[4];
#pragma unroll
    for (int j = 0; j < 4; j++) bb[j] = bias[nBase + tn + j];

#pragma unroll
    for (int i = 0; i < 8; i++) {
        *(float4*)(C + (size_t)(mBase + tm + i) * ldc + nBase + tn) =
            make_float4(acc[i][0] + bb[0], acc[i][1] + bb[1],
                        acc[i][2] + bb[2], acc[i][3] + bb[3]);
    }
}

// =====================================================================
// tokens gather + bf16 hi/lo split fused
// =====================================================================
__global__ void tokens_split_kernel(float* __restrict__ out_tokens,
                                    __nv_bfloat16* __restrict__ tokHi,
                                    __nv_bfloat16* __restrict__ tokLo)
{
    int idx = blockIdx.x * blockDim.x + threadIdx.x;
    if (idx >= MROWS * TOK_) return;
    int t   = idx % TOK_;
    int row = idx / TOK_;
    int n   = row % N_;
    int b   = row / N_;
    int d   = t / P_;
    int p   = t % P_;
    float v = g_aligned[((size_t)(b * T_ + n + p)) * D_ + d];
    out_tokens[idx] = v;
    __nv_bfloat16 h = __float2bfloat16(v);
    tokHi[idx] = h;
    tokLo[idx] = __float2bfloat16(v - __bfloat162float(h));
}

// =====================================================================
// RMS norm + bf16 hi/lo split fused
// =====================================================================
__global__ __launch_bounds__(128) void rms_split_kernel(
    const float* __restrict__ scale,
    __nv_bfloat16* __restrict__ hHi, __nv_bfloat16* __restrict__ hLo)
{
    int row = blockIdx.x;
    const float* h = g_h + (size_t)row * H_;
    int tid = threadIdx.x;

    float4 x = *(const float4*)(h + tid * 4);
    float ss = x.x * x.x + x.y * x.y + x.z * x.z + x.w * x.w;
#pragma unroll
    for (int o = 16; o; o >>= 1) ss += __shfl_xor_sync(0xffffffffu, ss, o);

    __shared__ float wsum[4];
    if ((tid & 31) == 0) wsum[tid >> 5] = ss;
    __syncthreads();
    float tot = wsum[0] + wsum[1] + wsum[2] + wsum[3];
    float inv = rsqrtf(tot * (1.0f / H_) + 1e-6f);

    float4 sc = *(const float4*)(scale + tid * 4);
    float v[4] = { x.x * inv * sc.x, x.y * inv * sc.y,
                   x.z * inv * sc.z, x.w * inv * sc.w };
    __nv_bfloat16 hi[4], lo[4];
#pragma unroll
    for (int j = 0; j < 4; j++) {
        hi[j] = __float2bfloat16(v[j]);
        lo[j] = __float2bfloat16(v[j] - __bfloat162float(hi[j]));
    }
    *(uint2*)(hHi + (size_t)row * H_ + tid * 4) = *(uint2*)hi;
    *(uint2*)(hLo + (size_t)row * H_ + tid * 4) = *(uint2*)lo;
}

// =====================================================================
// GRU v6 (tensor-core, fast gates): structure identical to proven v5;
// only the gate transcendentals switch to MUFU approximations
// (ex2.approx + rcp.approx sigmoid; tanh.approx).
// =====================================================================
#define GRU_BLOCKS 128
// smem byte offsets
#define GS_WHI 0                          // 8 chunks * 48 rows * 128B = 49152
#define GS_WLO 49152
#define GS_HHI 98304                      // 8 chunks * 16 rows * 128B = 16384
#define GS_HLO 114688
#define GS_RED 131072                     // 8 warps * 768 fp32 = 24576
#define GS_BHH 155648                     // 48 fp32
#define GRU_DSMEM (155648 + 192)

__global__ void gru_init_kernel()
{
    int idx = blockIdx.x * blockDim.x + threadIdx.x;
    __nv_bfloat16* ph = &g_hsHi[0][0][0];
    __nv_bfloat16* pl = &g_hsLo[0][0][0];
    if (idx < 2 * B_ * H_) { ph[idx] = __float2bfloat16(0.f); pl[idx] = __float2bfloat16(0.f); }
    if (idx < 4*32) g_gctr[idx] = 0u;
}

__device__ __forceinline__ void gbar_group(unsigned* ctr, unsigned target)
{
    __threadfence();
    __syncthreads();
    if (threadIdx.x == 0) {
        atomicAdd(ctr, 1u);
        unsigned v;
        do {
            asm volatile("ld.acquire.gpu.u32 %0, [%1];" : "=r"(v) : "l"(ctr));
        } while (v < target);
    }
    __syncthreads();
}

__global__ __launch_bounds__(256, 1) void gru_kernel(
    const __nv_bfloat16* __restrict__ whhHi, const __nv_bfloat16* __restrict__ whhLo,
    const float* __restrict__ bhh,
    __nv_bfloat16* __restrict__ hidHi, __nv_bfloat16* __restrict__ hidLo)
{
    extern __shared__ char gsm[];
    const uint32_t sB = smem_u32(gsm);
    float* red  = (float*)(gsm + GS_RED);
    float* sbhh = (float*)(gsm + GS_BHH);

    const int bid  = blockIdx.x;
    const int cg   = bid >> 2;        // col-group 0..31
    const int bg   = bid & 3;         // batch-group 0..3
    const int tid  = threadIdx.x;
    const int warp = tid >> 5;
    const int lane = tid & 31;
    const int col0 = cg * 16;
    unsigned* myctr = &g_gctr[bg * 32];

    // ---- one-time: weights (48 rows = [r|z|n] x 16 cols) into swizzled tiles
    for (int idx = tid; idx < 48 * H_; idx += 256) {
        int k = idx & (H_ - 1);
        int r = idx >> 9;
        int g = r >> 4, c = r & 15;
        size_t gidx = (size_t)(g * H_ + col0 + c) * H_ + k;
        int kc = k >> 6, cc = (k >> 3) & 7, off = k & 7;
        uint32_t so = (uint32_t)(kc * 6144 + r * 128 + ((cc ^ (r & 7)) << 4) + off * 2);
        *(__nv_bfloat16*)(gsm + GS_WHI + so) = whhHi[gidx];
        *(__nv_bfloat16*)(gsm + GS_WLO + so) = whhLo[gidx];
    }
    if (tid < 48) {
        int g = tid >> 4, c = tid & 15;
        sbhh[tid] = bhh[g * H_ + col0 + c];
    }
    __syncthreads();

    const int lane16 = lane & 15;
    const int lanehi = lane >> 4;
    const int brow_off = (lane & 7) + ((lane >> 4) << 3);
    const int bchi     = (lane >> 3) & 1;
    const int g  = lane >> 2;
    const int t  = lane & 3;

    const int b_out  = tid >> 4;      // 0..15 (output batch)
    const int hc     = tid & 15;      // output hidden col (local)
    const int gbo    = bg * 16 + b_out;
    const int ocol   = col0 + hc;
    const int hk = ocol;
    const uint32_t hpOff = (uint32_t)((hk >> 6) * 2048 + b_out * 128 +
                           ((((hk >> 3) & 7) ^ (b_out & 7)) << 4) + (hk & 7) * 2);

    int cur = 0;
    for (int n = 0; n < N_; n++) {
        // ---- stage 16-batch h slice (hi+lo, 32KB) into swizzled tiles
#pragma unroll
        for (int q = 0; q < 8; q++) {
            int id  = tid * 8 + q;              // 0..2047
            int ten = id >> 10;                 // 0 hi, 1 lo
            int rem = id & 1023;
            int r   = rem >> 6;                 // batch row 0..15
            int cu  = rem & 63;                 // 16B unit in row
            int kc  = cu >> 3, cc = cu & 7;
            uint32_t dst = sB + (ten ? GS_HLO : GS_HHI)
                         + (uint32_t)(kc * 2048 + r * 128 + ((cc ^ (r & 7)) << 4));
            const __nv_bfloat16* src = ten
                ? &g_hsLo[cur][bg*16 + r][kc*64 + cc*8]
                : &g_hsHi[cur][bg*16 + r][kc*64 + cc*8];
            asm volatile("cp.async.cg.shared.global [%0], [%1], 16;"
                         :: "r"(dst), "l"(src));
        }
        asm volatile("cp.async.commit_group;");

        // gx prefetch (overlaps staging)
        const float* gx = g_gx + ((size_t)(gbo * N_ + n)) * H3;
        float gxr = __ldg(gx + ocol);
        float gxz = __ldg(gx + H_ + ocol);
        float gxn = __ldg(gx + 2*H_ + ocol);

        asm volatile("cp.async.wait_group 0;");
        __syncthreads();

        // ---- warp w: K slice [w*64, w*64+64), M=16, N=48 (6 n-tiles)
        float acc[6][4];
#pragma unroll
        for (int nt = 0; nt < 6; nt++)
#pragma unroll
            for (int c = 0; c < 4; c++) acc[nt][c] = 0.f;

        const uint32_t hHiB = sB + GS_HHI + warp * 2048;
        const uint32_t hLoB = sB + GS_HLO + warp * 2048;
        const uint32_t wHiB = sB + GS_WHI + warp * 6144;
        const uint32_t wLoB = sB + GS_WLO + warp * 6144;

#pragma unroll
        for (int ks = 0; ks < 4; ks++) {
            uint32_t ah[4], al[4];
            {
                int row = lane16;
                uint32_t off = (uint32_t)(row * 128 + (((ks*2 + lanehi) ^ (row & 7)) << 4));
                ldsm4(ah, hHiB + off);
                ldsm4(al, hLoB + off);
            }
#pragma unroll
            for (int np = 0; np < 3; np++) {
                int row = np*16 + brow_off;
                uint32_t off = (uint32_t)(row * 128 + (((ks*2 + bchi) ^ (row & 7)) << 4));
                uint32_t r4[4];
                uint32_t bh0[2], bh1[2], bl0[2], bl1[2];
                ldsm4(r4, wHiB + off);
                bh0[0] = r4[0]; bh0[1] = r4[1];
                bh1[0] = r4[2]; bh1[1] = r4[3];
                ldsm4(r4, wLoB + off);
                bl0[0] = r4[0]; bl0[1] = r4[1];
                bl1[0] = r4[2]; bl1[1] = r4[3];
                mma_bf16(acc[2*np],     ah, bh0);
                mma_bf16(acc[2*np],     ah, bl0);
                mma_bf16(acc[2*np],     al, bh0);
                mma_bf16(acc[2*np + 1], ah, bh1);
                mma_bf16(acc[2*np + 1], ah, bl1);
                mma_bf16(acc[2*np + 1], al, bh1);
            }
        }

        // ---- store per-warp partials: red[warp][row*48 + col]
        {
            float* rw = red + warp * 768;
#pragma unroll
            for (int nt = 0; nt < 6; nt++) {
                int c0 = nt*8 + 2*t;
                *(float2*)(rw + g * 48 + c0)       = make_float2(acc[nt][0], acc[nt][1]);
                *(float2*)(rw + (g + 8) * 48 + c0) = make_float2(acc[nt][2], acc[nt][3]);
            }
        }
        // hp read (from staged smem): hi + lo
        float hp;
        {
            __nv_bfloat16 phi = *(__nv_bfloat16*)(gsm + GS_HHI + hpOff);
            __nv_bfloat16 plo = *(__nv_bfloat16*)(gsm + GS_HLO + hpOff);
            hp = __bfloat162float(phi) + __bfloat162float(plo);
        }
        __syncthreads();

        // ---- reduce 8 warps, fast gate math, one output per thread
        float s0 = 0.f, s1 = 0.f, s2 = 0.f;
#pragma unroll
        for (int w = 0; w < 8; w++) {
            const float* rw = red + w * 768 + b_out * 48;
            s0 += rw[hc];
            s1 += rw[16 + hc];
            s2 += rw[32 + hc];
        }
        float r  = sigmoid_fast(gxr + s0 + sbhh[hc]);
        float z  = sigmoid_fast(gxz + s1 + sbhh[16 + hc]);
        float nn = tanh_fast(gxn + r * (s2 + sbhh[32 + hc]));
        float hn = (1.0f - z) * nn + z * hp;

        __nv_bfloat16 oh = __float2bfloat16(hn);
        __nv_bfloat16 ol = __float2bfloat16(hn - __bfloat162float(oh));
        g_hsHi[cur ^ 1][gbo][ocol] = oh;
        g_hsLo[cur ^ 1][gbo][ocol] = ol;
        size_t base = ((size_t)(gbo * N_ + n)) * H_ + ocol;
        hidHi[base] = oh;
        hidLo[base] = ol;

        gbar_group(myctr, (unsigned)(n + 1) * 32u);
        cur ^= 1;
    }
}

// =====================================================================
// host side
// =====================================================================
#define BG_DSMEM  (2 * STGB)   // 131072 B

static void launch_split(const float* src, __nv_bfloat16* hi, __nv_bfloat16* lo, size_t n)
{
    int n4 = (int)(n / 4);
    split_kernel<<<(n4 + 255) / 256, 256>>>((const float4*)src, (uint2*)hi, (uint2*)lo, n4);
}

extern "C" void kernel_launch(void* const* d_in, const int* in_sizes, int n_in,
                              void* d_out, int out_size)
{
    const float* x      = (const float*)d_in[0];
    const int*   sidx   = (const int*)  d_in[1];
    const float* sW     = (const float*)d_in[2];
    const float* sb     = (const float*)d_in[3];
    const float* projW  = (const float*)d_in[4];
    const float* projb  = (const float*)d_in[5];
    const float* rscale = (const float*)d_in[6];
    const float* Wih    = (const float*)d_in[7];
    const float* Whh    = (const float*)d_in[8];
    const float* bih    = (const float*)d_in[9];
    const float* bhh    = (const float*)d_in[10];
    const float* W1     = (const float*)d_in[11];
    const float* b1     = (const float*)d_in[12];
    const float* W2     = (const float*)d_in[13];
    const float* b2     = (const float*)d_in[14];

    float* out        = (float*)d_out;
    float* out_preds  = out;
    float* out_tokens = out + (size_t)K_H * MROWS * TOK_;

    float *pAligned, *pH, *pGx;
    cudaGetSymbolAddress((void**)&pAligned, g_aligned);
    cudaGetSymbolAddress((void**)&pH,       g_h);
    cudaGetSymbolAddress((void**)&pGx,      g_gx);

    __nv_bfloat16 *tokHi, *tokLo, *hHi, *hLo, *hidHi, *hidLo, *actHi, *actLo;
    __nv_bfloat16 *pwHi, *pwLo, *wihHi, *wihLo, *whhHi, *whhLo, *w1Hi, *w1Lo, *w2Hi, *w2Lo;
    cudaGetSymbolAddress((void**)&tokHi, g_tokHi); cudaGetSymbolAddress((void**)&tokLo, g_tokLo);
    cudaGetSymbolAddress((void**)&hHi,   g_hHi);   cudaGetSymbolAddress((void**)&hLo,   g_hLo);
    cudaGetSymbolAddress((void**)&hidHi, g_hidHi); cudaGetSymbolAddress((void**)&hidLo, g_hidLo);
    cudaGetSymbolAddress((void**)&actHi, g_actHi); cudaGetSymbolAddress((void**)&actLo, g_actLo);
    cudaGetSymbolAddress((void**)&pwHi,  g_pwHi);  cudaGetSymbolAddress((void**)&pwLo,  g_pwLo);
    cudaGetSymbolAddress((void**)&wihHi, g_wihHi); cudaGetSymbolAddress((void**)&wihLo, g_wihLo);
    cudaGetSymbolAddress((void**)&whhHi, g_whhHi); cudaGetSymbolAddress((void**)&whhLo, g_whhLo);
    cudaGetSymbolAddress((void**)&w1Hi,  g_w1Hi);  cudaGetSymbolAddress((void**)&w1Lo,  g_w1Lo);
    cudaGetSymbolAddress((void**)&w2Hi,  g_w2Hi);  cudaGetSymbolAddress((void**)&w2Lo,  g_w2Lo);

    static int attr_set = 0;
    if (!attr_set) {
        cudaFuncSetAttribute(bgemm_kernel,
                             cudaFuncAttributeMaxDynamicSharedMemorySize, BG_DSMEM);
        cudaFuncSetAttribute(gru_kernel,
                             cudaFuncAttributeMaxDynamicSharedMemorySize, GRU_DSMEM);
        attr_set = 1;
    }

    // 0) proj weight split
    launch_split(projW, pwHi, pwLo, (size_t)H_ * TOK_);

    // 1) session alignment (fp32 — feeds tokens output)
    sgemm_kernel<<<dim3(D_ / BN, T_ / BM, B_), 256>>>(
        x, D_, sW, D_, sb, pAligned, D_,
        T_, D_, D_,
        sidx, (size_t)T_ * D_, (size_t)T_ * D_, (size_t)D_ * D_, (size_t)D_);

    // 2) tokens gather + split (fused)
    tokens_split_kernel<<<(MROWS * TOK_ + 255) / 256, 256>>>(out_tokens, tokHi, tokLo);

    // 3) proj GEMM
    bgemm_kernel<<<dim3(H_ / 128, MROWS / 128), 256, BG_DSMEM>>>(
        tokHi, tokLo, TOK_, pwHi, pwLo, TOK_, projb,
        pH, nullptr, nullptr, H_, TOK_, 0);

    // 4) RMS + split (fused)
    rms_split_kernel<<<MROWS, 128>>>(rscale, hHi, hLo);

    // 5) Wih + Whh splits
    launch_split(Wih, wihHi, wihLo, (size_t)H3 * H_);
    launch_split(Whh, whhHi, whhLo, (size_t)H3 * H_);

    // 6) gx = h @ Wih^T + bih
    bgemm_kernel<<<dim3(H3 / 128, MROWS / 128), 256, BG_DSMEM>>>(
        hHi, hLo, H_, wihHi, wihLo, H_, bih,
        pGx, nullptr, nullptr, H3, H_, 0);

    launch_split(W1, w1Hi, w1Lo, (size_t)H3 * H_);
    launch_split(W2, w2Hi, w2Lo, (size_t)K_H * TOK_ * H_);

    // 7) GRU recurrence (tensor-core step; fast gates; bf16 hi/lo hidden out)
    gru_init_kernel<<<(2 * B_ * H_ + 255) / 256, 256>>>();
    gru_kernel<<<GRU_BLOCKS, 256, GRU_DSMEM>>>(whhHi, whhLo, bhh, hidHi, hidLo);

    // 8) head1 (3 horizons fused, N=1536) + exact GELU -> bf16 hi/lo
    bgemm_kernel<<<dim3(H3 / 128, MROWS / 128), 256, BG_DSMEM>>>(
        hidHi, hidLo, H_, w1Hi, w1Lo, H_, b1,
        nullptr, actHi, actLo, H3, H_, 1);

    // 9) head2 per horizon -> preds
    for (int k = 0; k < K_H; k++) {
        bgemm_kernel<<<dim3(TOK_ / 128, MROWS / 128), 256, BG_DSMEM>>>(
            actHi + (size_t)k * H_, actLo + (size_t)k * H_, H3,
            w2Hi + (size_t)k * TOK_ * H_, w2Lo + (size_t)k * TOK_ * H_, H_,
            b2 + (size_t)k * TOK_,
            out_preds + (size_t)k * MROWS * TOK_, nullptr, nullptr, TOK_, H_, 0);
    }
}